// round 13
// baseline (speedup 1.0000x reference)
#include <cuda_runtime.h>
#include <cstdint>

#define Tn 4096
#define BHn 16
#define BHT 65536

__device__ float    d_qn2[BHT];
__device__ float    d_kn2[BHT];
__device__ int      d_MQ2i[BHn];
__device__ int      d_MK2i[BHn];
__device__ unsigned d_klsu[BHn];
__device__ float    d_qh[4*BHT];
__device__ float    d_kh[4*BHT];
__device__ int      d_qpos[4*BHT];
__device__ int      d_kpos[4*BHT];
__device__ unsigned d_qcode[BHT];
__device__ unsigned d_kcode[BHT];
__device__ float    d_kprime[16777216];
__device__ float    d_qprime[16777216];
__device__ float    d_ksum[BHn*256];
__device__ float    d_kvb[BHn*256*64];
__device__ float    d_qk1[BHT];
__device__ float    d_pls[BHT];
__device__ float    d_qkv[BHT*64];
__device__ float    d_obuf[4ll*BHT*64];
__device__ float    d_logits[4*BHT];
__device__ float    d_dsumg[4*BHT];

__device__ __forceinline__ unsigned fmap(float f){
    unsigned u=__float_as_uint(f); return (u&0x80000000u)?~u:(u|0x80000000u);
}
__device__ __forceinline__ float funmap(unsigned u){
    return (u&0x80000000u)?__uint_as_float(u&0x7FFFFFFFu):__uint_as_float(~u);
}
__device__ __forceinline__ unsigned long long pk2(float x,float y){
    unsigned long long r; asm("mov.b64 %0,{%1,%2};":"=l"(r):"f"(x),"f"(y)); return r;
}
__device__ __forceinline__ void upk2(float&x,float&y,unsigned long long v){
    asm("mov.b64 {%0,%1},%2;":"=f"(x),"=f"(y):"l"(v));
}
#define FMA2(d,a,b,c) asm("fma.rn.f32x2 %0,%1,%2,%3;":"=l"(d):"l"(a),"l"(b),"l"(c))

__global__ void k_init(){
    int i=blockIdx.x*256+threadIdx.x;
    if(i<16){ d_MQ2i[i]=0; d_MK2i[i]=0; d_klsu[i]=0u; }
    if(i<BHT){ d_qcode[i]=0u; d_kcode[i]=0u; }
    if(i<4096) d_ksum[i]=0.f;
    if(i<262144) d_kvb[i]=0.f;
}

__global__ void k_norms(const float* __restrict__ q,const float* __restrict__ k){
    int g=blockIdx.x*256+threadIdx.x;
    int bh=g>>12,t=g&4095,b=bh>>3,h2=bh&7;
    const float4* qp=(const float4*)(q+((size_t)(b*Tn+t)*8+h2)*64);
    const float4* kp=(const float4*)(k+((size_t)(b*Tn+t)*8+h2)*64);
    float sq=0.f,sk=0.f;
    #pragma unroll
    for(int i=0;i<16;i++){
        float4 a=qp[i]; sq+=a.x*a.x+a.y*a.y+a.z*a.z+a.w*a.w;
        float4 c=kp[i]; sk+=c.x*c.x+c.y*c.y+c.z*c.z+c.w*c.w;
    }
    d_qn2[g]=sq; d_kn2[g]=sk;
    atomicMax(&d_MQ2i[bh],__float_as_int(sq));
    atomicMax(&d_MK2i[bh],__float_as_int(sk));
}

__global__ void k_hash(const float* __restrict__ q,const float* __restrict__ k,
                       const float* __restrict__ alpha,const float* __restrict__ beta){
    __shared__ float sAl[264],sBe[4];
    int tid=threadIdx.x;
    for(int i=tid;i<264;i+=256) sAl[i]=alpha[i];
    if(tid<4) sBe[tid]=beta[tid];
    __syncthreads();
    int gid=blockIdx.x*256+tid;
    int which=gid>>16, g=gid&65535;
    int bh=g>>12,t=g&4095,b=bh>>3,h2=bh&7;
    const float* base=which?k:q;
    const float4* row=(const float4*)(base+((size_t)(b*Tn+t)*8+h2)*64);
    float a0=0,a1=0,a2=0,a3=0;
    #pragma unroll
    for(int j=0;j<16;j++){
        float4 v=row[j]; int e=j*4;
        a0=fmaf(v.x,sAl[e*4+0],a0);a1=fmaf(v.x,sAl[e*4+1],a1);a2=fmaf(v.x,sAl[e*4+2],a2);a3=fmaf(v.x,sAl[e*4+3],a3);
        a0=fmaf(v.y,sAl[e*4+4],a0);a1=fmaf(v.y,sAl[e*4+5],a1);a2=fmaf(v.y,sAl[e*4+6],a2);a3=fmaf(v.y,sAl[e*4+7],a3);
        a0=fmaf(v.z,sAl[e*4+8],a0);a1=fmaf(v.z,sAl[e*4+9],a1);a2=fmaf(v.z,sAl[e*4+10],a2);a3=fmaf(v.z,sAl[e*4+11],a3);
        a0=fmaf(v.w,sAl[e*4+12],a0);a1=fmaf(v.w,sAl[e*4+13],a1);a2=fmaf(v.w,sAl[e*4+14],a2);a3=fmaf(v.w,sAl[e*4+15],a3);
    }
    float n2=which?d_kn2[g]:d_qn2[g];
    float mq2=__int_as_float(d_MQ2i[bh]),mk2=__int_as_float(d_MK2i[bh]);
    float ext=sqrtf(fmaxf(mq2+mk2-n2,0.f));
    int ar=which?65:64;
    float* dst=which?d_kh:d_qh;
    float acc[4]={a0,a1,a2,a3};
    #pragma unroll
    for(int n=0;n<4;n++)
        dst[(n*BHn+bh)*Tn+t]=acc[n]+ext*sAl[ar*4+n]+sBe[n];
}

__global__ void k_sort(){
    __shared__ unsigned long long key[Tn];
    int bid=blockIdx.x,tid=threadIdx.x;   // 1024 threads
    int which=bid>>6, idx=bid&63;
    const float* hp=(which?d_kh:d_qh)+(size_t)idx*Tn;
    for(int i=tid;i<Tn;i+=1024){
        unsigned u=__float_as_uint(hp[i]);
        u=(u&0x80000000u)?~u:(u|0x80000000u);
        key[i]=((unsigned long long)u<<32)|(unsigned)i;
    }
    __syncthreads();
    for(int k2=2;k2<=Tn;k2<<=1)
        for(int j=k2>>1;j>0;j>>=1){
            for(int i=tid;i<Tn;i+=1024){
                int ixj=i^j;
                if(ixj>i){
                    unsigned long long a=key[i],b=key[ixj];
                    if((a>b)==((i&k2)==0)){ key[i]=b; key[ixj]=a; }
                }
            }
            __syncthreads();
        }
    int hsh=idx>>4,bh=idx&15;
    int* pdst=(which?d_kpos:d_qpos)+(size_t)idx*Tn;
    unsigned* cdst=which?d_kcode:d_qcode;
    for(int i=tid;i<Tn;i+=1024){
        int tok=(int)(key[i]&0xffffffffu);
        pdst[i]=tok;
        atomicOr(&cdst[bh*Tn+tok],(unsigned)(i>>7)<<(8*hsh));
    }
}

// ---- k features: FMA2 GEMM, logv -> d_kprime, block max ----
__global__ void __launch_bounds__(256) k_featmax(const float* __restrict__ x,
                                                 const float* __restrict__ proj){
    __shared__ float sX[64*33];
    __shared__ float sPT[32*258];
    __shared__ float sRed[256];
    int bx=blockIdx.x; int bh=bx>>6; int tile=bx&63; int t0=tile*64;
    int tid=threadIdx.x,ty=tid>>4,tx=tid&15;
    int b=bh>>3,h2=bh&7;
    unsigned long long acc2[4][8];
    #pragma unroll
    for(int u=0;u<4;u++)
        #pragma unroll
        for(int w=0;w<8;w++) acc2[u][w]=0ull;
    for(int ec=0;ec<2;ec++){
        __syncthreads();
        for(int i=tid;i<2048;i+=256){ int r=i>>5,e=i&31;
            sX[r*33+e]=x[((size_t)(b*Tn+t0+r)*8+h2)*64+ec*32+e]; }
        for(int i=tid;i<8192;i+=256){ int m=i>>5,e=i&31;
            sPT[e*258+m]=proj[m*64+ec*32+e]; }
        __syncthreads();
        #pragma unroll 4
        for(int e=0;e<32;e++){
            unsigned long long a2[4],b2[8];
            #pragma unroll
            for(int u=0;u<4;u++){ float av=sX[(u*16+ty)*33+e]; a2[u]=pk2(av,av); }
            #pragma unroll
            for(int w=0;w<8;w++) b2[w]=*(const unsigned long long*)&sPT[e*258+w*32+tx*2];
            #pragma unroll
            for(int u=0;u<4;u++)
                #pragma unroll
                for(int w=0;w<8;w++) FMA2(acc2[u][w],a2[u],b2[w],acc2[u][w]);
        }
    }
    float mx=-3.4e38f;
    #pragma unroll
    for(int u=0;u<4;u++){
        int row=u*16+ty;
        float dg=0.0625f*d_kn2[bh*Tn+t0+row];
        #pragma unroll
        for(int w=0;w<8;w++){
            float v0,v1; upk2(v0,v1,acc2[u][w]);
            float lv0=0.35355339059327373f*v0-dg;
            float lv1=0.35355339059327373f*v1-dg;
            mx=fmaxf(mx,fmaxf(lv0,lv1));
            *(float2*)&d_kprime[((size_t)bh*Tn+t0+row)*256+w*32+tx*2]=make_float2(lv0,lv1);
        }
    }
    sRed[tid]=mx; __syncthreads();
    for(int s=128;s;s>>=1){ if(tid<s) sRed[tid]=fmaxf(sRed[tid],sRed[tid+s]); __syncthreads(); }
    if(tid==0) atomicMax(&d_klsu[bh],fmap(sRed[0]));
}

// ---- kv = k'^T @ V (FMA2, fused exp+writeback+ksum) ----
__global__ void __launch_bounds__(256) k_kv(const float* __restrict__ v){
    __shared__ float sKP[32*65],sV[32*66];
    int split=blockIdx.x,mt=blockIdx.y,bh=blockIdx.z;
    int m0=mt*64,s0=split*512;
    int tid=threadIdx.x,ty=tid>>4,tx=tid&15;
    int b=bh>>3,h2=bh&7;
    float kls=funmap(d_klsu[bh]);
    unsigned long long acc2[4][2];
    #pragma unroll
    for(int u=0;u<4;u++){ acc2[u][0]=0ull; acc2[u][1]=0ull; }
    float ksp=0.f;
    for(int sb=0;sb<512;sb+=32){
        __syncthreads();
        for(int i=tid;i<2048;i+=256){ int r=i>>6,cc=i&63;
            size_t gi=((size_t)bh*Tn+s0+sb+r)*256+m0+cc;
            float lv=d_kprime[gi];
            float kp=__expf(lv-kls)*0.0625f;
            d_kprime[gi]=kp;
            sKP[r*65+cc]=kp;
            ksp+=kp;
            sV[r*66+cc]=v[((size_t)(b*Tn+s0+sb+r)*8+h2)*64+cc]; }
        __syncthreads();
        #pragma unroll 4
        for(int s=0;s<32;s++){
            unsigned long long a2[4],b2[2];
            #pragma unroll
            for(int u=0;u<4;u++){ float av=sKP[s*65+u*16+ty]; a2[u]=pk2(av,av); }
            b2[0]=*(const unsigned long long*)&sV[s*66+tx*2];
            b2[1]=*(const unsigned long long*)&sV[s*66+32+tx*2];
            #pragma unroll
            for(int u=0;u<4;u++){
                FMA2(acc2[u][0],a2[u],b2[0],acc2[u][0]);
                FMA2(acc2[u][1],a2[u],b2[1],acc2[u][1]);
            }
        }
    }
    atomicAdd(&d_ksum[bh*256+m0+(tid&63)],ksp);
    #pragma unroll
    for(int u=0;u<4;u++)
        #pragma unroll
        for(int w2=0;w2<2;w2++){
            float o0,o1; upk2(o0,o1,acc2[u][w2]);
            atomicAdd(&d_kvb[(bh*256+m0+u*16+ty)*64+w2*32+tx*2],o0);
            atomicAdd(&d_kvb[(bh*256+m0+u*16+ty)*64+w2*32+tx*2+1],o1);
        }
}

// ---- q features (FMA2): stab, pls, q', qk1 ----
__global__ void __launch_bounds__(256) k_qfeatg(const float* __restrict__ x,
                                                const float* __restrict__ proj){
    __shared__ float sX[64*33];
    __shared__ float sPT[32*258];
    __shared__ float sRed[64*17];
    __shared__ float sStab[64];
    __shared__ float sKsum[256];
    int bx=blockIdx.x; int bh=bx>>6; int tile=bx&63; int t0=tile*64;
    int tid=threadIdx.x,ty=tid>>4,tx=tid&15;
    int b=bh>>3,h2=bh&7;
    sKsum[tid]=d_ksum[bh*256+tid];
    unsigned long long acc2[4][8];
    #pragma unroll
    for(int u=0;u<4;u++)
        #pragma unroll
        for(int w=0;w<8;w++) acc2[u][w]=0ull;
    for(int ec=0;ec<2;ec++){
        __syncthreads();
        for(int i=tid;i<2048;i+=256){ int r=i>>5,e=i&31;
            sX[r*33+e]=x[((size_t)(b*Tn+t0+r)*8+h2)*64+ec*32+e]; }
        for(int i=tid;i<8192;i+=256){ int m=i>>5,e=i&31;
            sPT[e*258+m]=proj[m*64+ec*32+e]; }
        __syncthreads();
        #pragma unroll 4
        for(int e=0;e<32;e++){
            unsigned long long a2[4],b2[8];
            #pragma unroll
            for(int u=0;u<4;u++){ float av=sX[(u*16+ty)*33+e]; a2[u]=pk2(av,av); }
            #pragma unroll
            for(int w=0;w<8;w++) b2[w]=*(const unsigned long long*)&sPT[e*258+w*32+tx*2];
            #pragma unroll
            for(int u=0;u<4;u++)
                #pragma unroll
                for(int w=0;w<8;w++) FMA2(acc2[u][w],a2[u],b2[w],acc2[u][w]);
        }
    }
    float kls=funmap(d_klsu[bh]);
    #pragma unroll
    for(int u=0;u<4;u++){
        int row=u*16+ty;
        float dg=0.0625f*d_qn2[bh*Tn+t0+row];
        float rm=-3.4e38f;
        #pragma unroll
        for(int w=0;w<8;w++){
            float v0,v1; upk2(v0,v1,acc2[u][w]);
            float lv0=0.35355339059327373f*v0-dg;
            float lv1=0.35355339059327373f*v1-dg;
            rm=fmaxf(rm,fmaxf(lv0,lv1));
            acc2[u][w]=pk2(lv0,lv1);
        }
        sRed[row*17+tx]=rm;
    }
    __syncthreads();
    if(tid<64){
        float m=sRed[tid*17];
        #pragma unroll
        for(int c=1;c<16;c++) m=fmaxf(m,sRed[tid*17+c]);
        sStab[tid]=m;
        d_pls[bh*Tn+t0+tid]=m+kls;
    }
    __syncthreads();
    float part[4]={};
    #pragma unroll
    for(int u=0;u<4;u++){
        int row=u*16+ty;
        float st=sStab[row];
        #pragma unroll
        for(int w=0;w<8;w++){
            float lv0,lv1; upk2(lv0,lv1,acc2[u][w]);
            float qp0=__expf(lv0-st)*0.0625f;
            float qp1=__expf(lv1-st)*0.0625f;
            *(float2*)&d_qprime[((size_t)bh*Tn+t0+row)*256+w*32+tx*2]=make_float2(qp0,qp1);
            part[u]=fmaf(qp0,sKsum[w*32+tx*2],part[u]);
            part[u]=fmaf(qp1,sKsum[w*32+tx*2+1],part[u]);
        }
    }
    __syncthreads();
    #pragma unroll
    for(int u=0;u<4;u++) sRed[(u*16+ty)*17+tx]=part[u];
    __syncthreads();
    if(tid<64){
        float s=0.f;
        #pragma unroll
        for(int c=0;c<16;c++) s+=sRed[tid*17+c];
        d_qk1[bh*Tn+t0+tid]=s;
    }
}

// ---- qkv = q' @ kv (FMA2) ----
__global__ void __launch_bounds__(256) k_qkv(){
    __shared__ float sQ[64*33],sKV[32*66];
    int tile=blockIdx.x,bh=blockIdx.y,t0=tile*64;
    int tid=threadIdx.x,ty=tid>>4,tx=tid&15;
    unsigned long long acc2[4][2];
    #pragma unroll
    for(int u=0;u<4;u++){ acc2[u][0]=0ull; acc2[u][1]=0ull; }
    for(int c=0;c<8;c++){
        __syncthreads();
        for(int i=tid;i<2048;i+=256){ int r=i>>5,m=i&31;
            sQ[r*33+m]=d_qprime[((size_t)bh*Tn+t0+r)*256+c*32+m]; }
        for(int i=tid;i<2048;i+=256){ int m=i>>6,dd=i&63;
            sKV[m*66+dd]=d_kvb[(bh*256+c*32+m)*64+dd]; }
        __syncthreads();
        #pragma unroll 4
        for(int m=0;m<32;m++){
            unsigned long long a2[4],b2[2];
            #pragma unroll
            for(int u=0;u<4;u++){ float av=sQ[(u*16+ty)*33+m]; a2[u]=pk2(av,av); }
            b2[0]=*(const unsigned long long*)&sKV[m*66+tx*2];
            b2[1]=*(const unsigned long long*)&sKV[m*66+32+tx*2];
            #pragma unroll
            for(int u=0;u<4;u++){
                FMA2(acc2[u][0],a2[u],b2[0],acc2[u][0]);
                FMA2(acc2[u][1],a2[u],b2[1],acc2[u][1]);
            }
        }
    }
    #pragma unroll
    for(int u=0;u<4;u++)
        #pragma unroll
        for(int w2=0;w2<2;w2++){
            float o0,o1; upk2(o0,o1,acc2[u][w2]);
            *(float2*)&d_qkv[((size_t)bh*Tn+t0+u*16+ty)*64+w2*32+tx*2]=make_float2(o0,o1);
        }
}

// dyn smem floats: sInner 16512 | 4x(A 4352 + BT 4224) | meta 896
#define S_A0 16512
#define S_BT0 20864
#define S_A1 25088
#define S_BT1 29312
#define S_A2 33536
#define S_BT2 37760
#define S_A3 41984
#define S_BT3 46208
#define S_META 50432
#define ATTN_SMEM_BYTES ((S_META+896)*4)

__global__ void __launch_bounds__(512,1) k_attn(const float* __restrict__ q,
                                                const float* __restrict__ k,
                                                const float* __restrict__ v){
    extern __shared__ float dyn[];
    float* sInner=dyn;
    int* sQt=(int*)(dyn+S_META);
    int* sKt=(int*)(dyn+S_META+128);
    unsigned* sQC=(unsigned*)(dyn+S_META+256);
    unsigned* sKC=(unsigned*)(dyn+S_META+384);
    float* sPls=dyn+S_META+512;
    float* sLse=dyn+S_META+640;
    float* sPexp=dyn+S_META+768;
    const int AOF[4]={S_A0,S_A1,S_A2,S_A3};
    const int BOF[4]={S_BT0,S_BT1,S_BT2,S_BT3};
    int n=blockIdx.x,bh=blockIdx.y,h=blockIdx.z;
    int b=bh>>3,h2=bh&7,hb=h*BHn+bh;
    int tid=threadIdx.x,ty=tid>>4,tx=tid&15;
    if(tid<128){
        int qt=d_qpos[(size_t)hb*Tn+n*128+tid];
        int kt=d_kpos[(size_t)hb*Tn+n*128+tid];
        sQt[tid]=qt; sKt[tid]=kt;
        sQC[tid]=d_qcode[bh*Tn+qt]; sKC[tid]=d_kcode[bh*Tn+kt];
        sPls[tid]=d_pls[bh*Tn+qt];
    }
    __syncthreads();
    // ===== phase 1: inner = Q K^T =====
    unsigned long long accI[4][4];
    #pragma unroll
    for(int u=0;u<4;u++)
        #pragma unroll
        for(int w=0;w<4;w++) accI[u][w]=0ull;
    float4 qa[2],ka[2];
    #pragma unroll
    for(int j2=0;j2<2;j2++){
        int idx=tid+j2*512; int r=idx>>3,seg=idx&7;
        qa[j2]=*(const float4*)&q[((size_t)(b*Tn+sQt[r])*8+h2)*64+seg*4];
        ka[j2]=*(const float4*)&k[((size_t)(b*Tn+sKt[r])*8+h2)*64+seg*4];
    }
    {
        float* sA=dyn+S_A0; float* sBT=dyn+S_BT0;
        #pragma unroll
        for(int j2=0;j2<2;j2++){
            int idx=tid+j2*512; int r=idx>>3,seg=idx&7;
            sA[r*33+seg*4+0]=qa[j2].x; sA[r*33+seg*4+1]=qa[j2].y;
            sA[r*33+seg*4+2]=qa[j2].z; sA[r*33+seg*4+3]=qa[j2].w;
            sBT[(seg*4+0)*130+r]=ka[j2].x; sBT[(seg*4+1)*130+r]=ka[j2].y;
            sBT[(seg*4+2)*130+r]=ka[j2].z; sBT[(seg*4+3)*130+r]=ka[j2].w;
        }
    }
    #pragma unroll
    for(int j2=0;j2<2;j2++){
        int idx=tid+j2*512; int r=idx>>3,seg=idx&7;
        qa[j2]=*(const float4*)&q[((size_t)(b*Tn+sQt[r])*8+h2)*64+32+seg*4];
        ka[j2]=*(const float4*)&k[((size_t)(b*Tn+sKt[r])*8+h2)*64+32+seg*4];
    }
    __syncthreads();
    for(int ec=0;ec<2;ec++){
        float* sA=dyn+(ec?S_A1:S_A0); float* sBT=dyn+(ec?S_BT1:S_BT0);
        #pragma unroll 4
        for(int e=0;e<32;e++){
            unsigned long long a2[4],b2[4];
            #pragma unroll
            for(int u=0;u<4;u++){ float av=sA[(u*32+ty)*33+e]; a2[u]=pk2(av,av); }
            #pragma unroll
            for(int w=0;w<4;w++) b2[w]=*(const unsigned long long*)&sBT[e*130+w*32+tx*2];
            #pragma unroll
            for(int u=0;u<4;u++)
                #pragma unroll
                for(int w=0;w<4;w++) FMA2(accI[u][w],a2[u],b2[w],accI[u][w]);
        }
        if(ec==0){
            float* sA1=dyn+S_A1; float* sBT1=dyn+S_BT1;
            #pragma unroll
            for(int j2=0;j2<2;j2++){
                int idx=tid+j2*512; int r=idx>>3,seg=idx&7;
                sA1[r*33+seg*4+0]=qa[j2].x; sA1[r*33+seg*4+1]=qa[j2].y;
                sA1[r*33+seg*4+2]=qa[j2].z; sA1[r*33+seg*4+3]=qa[j2].w;
                sBT1[(seg*4+0)*130+r]=ka[j2].x; sBT1[(seg*4+1)*130+r]=ka[j2].y;
                sBT1[(seg*4+2)*130+r]=ka[j2].z; sBT1[(seg*4+3)*130+r]=ka[j2].w;
            }
            __syncthreads();
        }
    }
    const float ldt[4]={0.f,0.6931471805599453f,1.0986122886681098f,1.3862943611198906f};
    #pragma unroll
    for(int u=0;u<4;u++){
        int i=u*32+ty;
        unsigned qc=sQC[i];
        float rm=-3.4e38f;
        #pragma unroll
        for(int w=0;w<4;w++){
            int j0=w*32+tx*2;
            float v0,v1; upk2(v0,v1,accI[u][w]);
            int dup0=__popc(__vcmpeq4(qc,sKC[j0]))>>3;
            int dup1=__popc(__vcmpeq4(qc,sKC[j0+1]))>>3;
            float val0=v0*0.125f-ldt[dup0-1];
            float val1=v1*0.125f-ldt[dup1-1];
            sInner[i*129+j0]=val0; sInner[i*129+j0+1]=val1;
            rm=fmaxf(rm,fmaxf(val0,val1));
        }
        #pragma unroll
        for(int o=8;o;o>>=1) rm=fmaxf(rm,__shfl_xor_sync(0xffffffffu,rm,o,16));
        if(tx==0){
            float l=fmaxf(rm,sPls[i]);
            sLse[i]=l; sPexp[i]=__expf(sPls[i]-l);
        }
    }
    // ===== phase 2: dots_prime = q' k'^T (quad-buffer ring, chunk c -> buf[(c+2)&3]) =====
    unsigned long long accP[4][4];
    #pragma unroll
    for(int u=0;u<4;u++)
        #pragma unroll
        for(int w=0;w<4;w++) accP[u][w]=0ull;
    float4 pa[2],pb[2];
    {   // chunk 0 -> buf2 (fresh buffer; no phase-1 conflict)
        #pragma unroll
        for(int j2=0;j2<2;j2++){
            int idx=tid+j2*512; int r=idx>>3,seg=idx&7;
            pa[j2]=*(const float4*)&d_qprime[((size_t)bh*Tn+sQt[r])*256+seg*4];
            pb[j2]=*(const float4*)&d_kprime[((size_t)bh*Tn+sKt[r])*256+seg*4];
        }
        float* sA=dyn+S_A2; float* sBT=dyn+S_BT2;
        #pragma unroll
        for(int j2=0;j2<2;j2++){
            int idx=tid+j2*512; int r=idx>>3,seg=idx&7;
            sA[r*33+seg*4+0]=pa[j2].x; sA[r*33+seg*4+1]=pa[j2].y;
            sA[r*33+seg*4+2]=pa[j2].z; sA[r*33+seg*4+3]=pa[j2].w;
            sBT[(seg*4+0)*130+r]=pb[j2].x; sBT[(seg*4+1)*130+r]=pb[j2].y;
            sBT[(seg*4+2)*130+r]=pb[j2].z; sBT[(seg*4+3)*130+r]=pb[j2].w;
        }
    }
    {   // chunk 1 -> buf3 (fresh buffer)
        #pragma unroll
        for(int j2=0;j2<2;j2++){
            int idx=tid+j2*512; int r=idx>>3,seg=idx&7;
            pa[j2]=*(const float4*)&d_qprime[((size_t)bh*Tn+sQt[r])*256+32+seg*4];
            pb[j2]=*(const float4*)&d_kprime[((size_t)bh*Tn+sKt[r])*256+32+seg*4];
        }
        float* sA=dyn+S_A3; float* sBT=dyn+S_BT3;
        #pragma unroll
        for(int j2=0;j2<2;j2++){
            int idx=tid+j2*512; int r=idx>>3,seg=idx&7;
            sA[r*33+seg*4+0]=pa[j2].x; sA[r*33+seg*4+1]=pa[j2].y;
            sA[r*33+seg*4+2]=pa[j2].z; sA[r*33+seg*4+3]=pa[j2].w;
            sBT[(seg*4+0)*130+r]=pb[j2].x; sBT[(seg*4+1)*130+r]=pb[j2].y;
            sBT[(seg*4+2)*130+r]=pb[j2].z; sBT[(seg*4+3)*130+r]=pb[j2].w;
        }
    }
    // prefetch chunk 2
    #pragma unroll
    for(int j2=0;j2<2;j2++){
        int idx=tid+j2*512; int r=idx>>3,seg=idx&7;
        pa[j2]=*(const float4*)&d_qprime[((size_t)bh*Tn+sQt[r])*256+64+seg*4];
        pb[j2]=*(const float4*)&d_kprime[((size_t)bh*Tn+sKt[r])*256+64+seg*4];
    }
    __syncthreads();
    for(int c=0;c<8;c++){
        if(c<6){
            // store chunk c+2 -> buf[(c+4)&3] == buf[c&3]
            float* sA=dyn+AOF[c&3]; float* sBT=dyn+BOF[c&3];
            #pragma unroll
            for(int j2=0;j2<2;j2++){
                int idx=tid+j2*512; int r=idx>>3,seg=idx&7;
                sA[r*33+seg*4+0]=pa[j2].x; sA[r*33+seg*4+1]=pa[j2].y;
                sA[r*33+seg*4+2]=pa[j2].z; sA[r*33+seg*4+3]=pa[j2].w;
                sBT[(seg*4+0)*130+r]=pb[j2].x; sBT[(seg*4+1)*130+r]=pb[j2].y;
                sBT[(seg*4+2)*130+r]=pb[j2].z; sBT[(seg*4+3)*130+r]=pb[j2].w;
            }
            if(c<5){
                #pragma unroll
                for(int j2=0;j2<2;j2++){
                    int idx=tid+j2*512; int r=idx>>3,seg=idx&7;
                    pa[j2]=*(const float4*)&d_qprime[((size_t)bh*Tn+sQt[r])*256+(c+3)*32+seg*4];
                    pb[j2]=*(const float4*)&d_kprime[((size_t)bh*Tn+sKt[r])*256+(c+3)*32+seg*4];
                }
            }
        }
        float* sA=dyn+AOF[(c+2)&3]; float* sBT=dyn+BOF[(c+2)&3];
        #pragma unroll 4
        for(int m=0;m<32;m++){
            unsigned long long a2[4],b2[4];
            #pragma unroll
            for(int u=0;u<4;u++){ float av=sA[(u*32+ty)*33+m]; a2[u]=pk2(av,av); }
            #pragma unroll
            for(int w=0;w<4;w++) b2[w]=*(const unsigned long long*)&sBT[m*130+w*32+tx*2];
            #pragma unroll
            for(int u=0;u<4;u++)
                #pragma unroll
                for(int w=0;w<4;w++) FMA2(accP[u][w],a2[u],b2[w],accP[u][w]);
        }
        if(c&1) __syncthreads();
    }
    // ===== phase 3: dots + dots@V =====
    float* sDots=dyn+S_A0;
    float* sV=dyn+S_BT0;
    unsigned long long accO[4][2];
    #pragma unroll
    for(int u=0;u<4;u++){ accO[u][0]=0ull; accO[u][1]=0ull; }
    float rsum[4]={};
    for(int jc=0;jc<4;jc++){
        if(jc) __syncthreads();
        #pragma unroll
        for(int u=0;u<4;u++){
            int i=u*32+ty;
            float lse=sLse[i],pe=sPexp[i];
            unsigned qc=sQC[i];
            int j0=jc*32+tx*2;
            float p0,p1; upk2(p0,p1,accP[u][jc]);
            int dup0=__popc(__vcmpeq4(qc,sKC[j0]))>>3;
            int dup1=__popc(__vcmpeq4(qc,sKC[j0+1]))>>3;
            float dots0=__expf(sInner[i*129+j0]-lse)-(p0/(float)dup0)*pe;
            float dots1=__expf(sInner[i*129+j0+1]-lse)-(p1/(float)dup1)*pe;
            rsum[u]+=dots0+dots1;
            *(float2*)&sDots[i*34+tx*2]=make_float2(dots0,dots1);
        }
        {
            int jj=tid>>4, seg=tid&15;
            float4 va=*(const float4*)&v[((size_t)(b*Tn+sKt[jc*32+jj])*8+h2)*64+seg*4];
            *(float2*)&sV[jj*66+seg*4]=make_float2(va.x,va.y);
            *(float2*)&sV[jj*66+seg*4+2]=make_float2(va.z,va.w);
        }
        __syncthreads();
        #pragma unroll 4
        for(int jj=0;jj<32;jj++){
            unsigned long long dv2[4],vv2[2];
            #pragma unroll
            for(int u=0;u<4;u++){ float dvv=sDots[(u*32+ty)*34+jj]; dv2[u]=pk2(dvv,dvv); }
            vv2[0]=*(const unsigned long long*)&sV[jj*66+tx*2];
            vv2[1]=*(const unsigned long long*)&sV[jj*66+32+tx*2];
            #pragma unroll
            for(int u=0;u<4;u++){
                FMA2(accO[u][0],dv2[u],vv2[0],accO[u][0]);
                FMA2(accO[u][1],dv2[u],vv2[1],accO[u][1]);
            }
        }
    }
    #pragma unroll
    for(int u=0;u<4;u++){
        int i=u*32+ty;
        int qt=sQt[i];
        float rs=rsum[u];
        #pragma unroll
        for(int o=8;o;o>>=1) rs+=__shfl_xor_sync(0xffffffffu,rs,o,16);
        if(tx==0){
            d_logits[(size_t)hb*Tn+qt]=sLse[i];
            d_dsumg[(size_t)hb*Tn+qt]=rs;
        }
        #pragma unroll
        for(int w2=0;w2<2;w2++){
            float o0,o1; upk2(o0,o1,accO[u][w2]);
            *(float2*)&d_obuf[((size_t)hb*Tn+qt)*64+w2*32+tx*2]=make_float2(o0,o1);
        }
    }
}

__global__ void k_final(float* __restrict__ out){
    int gid=blockIdx.x*256+threadIdx.x;
    int bh=gid>>14,rr=gid&16383,t=rr>>2,gq=rr&3;
    int g=bh*Tn+t;
    float l[4],ds[4];
    #pragma unroll
    for(int h=0;h<4;h++){ l[h]=d_logits[(size_t)(h*BHn+bh)*Tn+t]; ds[h]=d_dsumg[(size_t)(h*BHn+bh)*Tn+t]; }
    float m=fmaxf(fmaxf(l[0],l[1]),fmaxf(l[2],l[3]));
    float s=__expf(l[0]-m)+__expf(l[1]-m)+__expf(l[2]-m)+__expf(l[3]-m);
    float nls=m+__logf(s);
    float ps=__expf(d_pls[g]-nls);
    float p[4];
    float norm=d_qk1[g]*ps;
    #pragma unroll
    for(int h=0;h<4;h++){ p[h]=__expf(l[h]-nls); norm=fmaf(ds[h],p[h],norm); }
    norm=fmaxf(norm,1e-6f);
    float inv=1.f/norm;
    int b=bh>>3,h2=bh&7;
    const float4* qkv4=(const float4*)(d_qkv+(size_t)g*64+gq*16);
    float4* o4=(float4*)(out+((size_t)(b*Tn+t)*8+h2)*64+gq*16);
    #pragma unroll
    for(int j=0;j<4;j++){
        float4 a=qkv4[j];
        float4 r; r.x=a.x*ps; r.y=a.y*ps; r.z=a.z*ps; r.w=a.w*ps;
        #pragma unroll
        for(int h=0;h<4;h++){
            const float4 ob=((const float4*)(d_obuf+((size_t)(h*BHn+bh)*Tn+t)*64+gq*16))[j];
            r.x=fmaf(ob.x,p[h],r.x); r.y=fmaf(ob.y,p[h],r.y);
            r.z=fmaf(ob.z,p[h],r.z); r.w=fmaf(ob.w,p[h],r.w);
        }
        r.x*=inv; r.y*=inv; r.z*=inv; r.w*=inv;
        o4[j]=r;
    }
}

extern "C" void kernel_launch(void* const* d_in, const int* in_sizes, int n_in,
                              void* d_out, int out_size){
    const float* q=(const float*)d_in[0];
    const float* k=(const float*)d_in[1];
    const float* v=(const float*)d_in[2];
    const float* proj=(const float*)d_in[3];
    const float* alpha=(const float*)d_in[4];
    const float* beta=(const float*)d_in[5];
    float* out=(float*)d_out;
    cudaFuncSetAttribute(k_attn, cudaFuncAttributeMaxDynamicSharedMemorySize, ATTN_SMEM_BYTES);
    k_init<<<1024,256>>>();
    k_norms<<<256,256>>>(q,k);
    k_hash<<<512,256>>>(q,k,alpha,beta);
    k_sort<<<128,1024>>>();
    k_featmax<<<1024,256>>>(k,proj);
    k_kv<<<dim3(8,4,16),256>>>(v);
    k_qfeatg<<<1024,256>>>(q,proj);
    k_qkv<<<dim3(64,16),256>>>();
    k_attn<<<dim3(32,16,4),512,ATTN_SMEM_BYTES>>>(q,k,v);
    k_final<<<1024,256>>>(out);
}

// round 14
// speedup vs baseline: 1.0284x; 1.0284x over previous
#include <cuda_runtime.h>
#include <cstdint>

#define Tn 4096
#define BHn 16
#define BHT 65536

__device__ float    d_qn2[BHT];
__device__ float    d_kn2[BHT];
__device__ int      d_MQ2i[BHn];
__device__ int      d_MK2i[BHn];
__device__ unsigned d_klsu[BHn];
__device__ float    d_qh[4*BHT];
__device__ float    d_kh[4*BHT];
__device__ int      d_qpos[4*BHT];
__device__ int      d_kpos[4*BHT];
__device__ unsigned d_qcode[BHT];
__device__ unsigned d_kcode[BHT];
__device__ float    d_kprime[16777216];
__device__ float    d_qprime[16777216];
__device__ float    d_ksum[BHn*256];
__device__ float    d_kvb[BHn*256*64];
__device__ float    d_qk1[BHT];
__device__ float    d_pls[BHT];
__device__ float    d_qkv[BHT*64];
__device__ float    d_obuf[4ll*BHT*64];
__device__ float    d_logits[4*BHT];
__device__ float    d_dsumg[4*BHT];

__device__ __forceinline__ unsigned fmap(float f){
    unsigned u=__float_as_uint(f); return (u&0x80000000u)?~u:(u|0x80000000u);
}
__device__ __forceinline__ float funmap(unsigned u){
    return (u&0x80000000u)?__uint_as_float(u&0x7FFFFFFFu):__uint_as_float(~u);
}
__device__ __forceinline__ unsigned long long pk2(float x,float y){
    unsigned long long r; asm("mov.b64 %0,{%1,%2};":"=l"(r):"f"(x),"f"(y)); return r;
}
__device__ __forceinline__ void upk2(float&x,float&y,unsigned long long v){
    asm("mov.b64 {%0,%1},%2;":"=f"(x),"=f"(y):"l"(v));
}
#define FMA2(d,a,b,c) asm("fma.rn.f32x2 %0,%1,%2,%3;":"=l"(d):"l"(a),"l"(b),"l"(c))

__global__ void k_init(){
    int i=blockIdx.x*256+threadIdx.x;
    if(i<16){ d_MQ2i[i]=0; d_MK2i[i]=0; d_klsu[i]=0u; }
    if(i<BHT){ d_qcode[i]=0u; d_kcode[i]=0u; }
    if(i<4096) d_ksum[i]=0.f;
    if(i<262144) d_kvb[i]=0.f;
}

__global__ void k_norms(const float* __restrict__ q,const float* __restrict__ k){
    int g=blockIdx.x*256+threadIdx.x;
    int bh=g>>12,t=g&4095,b=bh>>3,h2=bh&7;
    const float4* qp=(const float4*)(q+((size_t)(b*Tn+t)*8+h2)*64);
    const float4* kp=(const float4*)(k+((size_t)(b*Tn+t)*8+h2)*64);
    float sq=0.f,sk=0.f;
    #pragma unroll
    for(int i=0;i<16;i++){
        float4 a=qp[i]; sq+=a.x*a.x+a.y*a.y+a.z*a.z+a.w*a.w;
        float4 c=kp[i]; sk+=c.x*c.x+c.y*c.y+c.z*c.z+c.w*c.w;
    }
    d_qn2[g]=sq; d_kn2[g]=sk;
    atomicMax(&d_MQ2i[bh],__float_as_int(sq));
    atomicMax(&d_MK2i[bh],__float_as_int(sk));
}

__global__ void k_hash(const float* __restrict__ q,const float* __restrict__ k,
                       const float* __restrict__ alpha,const float* __restrict__ beta){
    __shared__ float sAl[264],sBe[4];
    int tid=threadIdx.x;
    for(int i=tid;i<264;i+=256) sAl[i]=alpha[i];
    if(tid<4) sBe[tid]=beta[tid];
    __syncthreads();
    int gid=blockIdx.x*256+tid;
    int which=gid>>16, g=gid&65535;
    int bh=g>>12,t=g&4095,b=bh>>3,h2=bh&7;
    const float* base=which?k:q;
    const float4* row=(const float4*)(base+((size_t)(b*Tn+t)*8+h2)*64);
    float a0=0,a1=0,a2=0,a3=0;
    #pragma unroll
    for(int j=0;j<16;j++){
        float4 v=row[j]; int e=j*4;
        a0=fmaf(v.x,sAl[e*4+0],a0);a1=fmaf(v.x,sAl[e*4+1],a1);a2=fmaf(v.x,sAl[e*4+2],a2);a3=fmaf(v.x,sAl[e*4+3],a3);
        a0=fmaf(v.y,sAl[e*4+4],a0);a1=fmaf(v.y,sAl[e*4+5],a1);a2=fmaf(v.y,sAl[e*4+6],a2);a3=fmaf(v.y,sAl[e*4+7],a3);
        a0=fmaf(v.z,sAl[e*4+8],a0);a1=fmaf(v.z,sAl[e*4+9],a1);a2=fmaf(v.z,sAl[e*4+10],a2);a3=fmaf(v.z,sAl[e*4+11],a3);
        a0=fmaf(v.w,sAl[e*4+12],a0);a1=fmaf(v.w,sAl[e*4+13],a1);a2=fmaf(v.w,sAl[e*4+14],a2);a3=fmaf(v.w,sAl[e*4+15],a3);
    }
    float n2=which?d_kn2[g]:d_qn2[g];
    float mq2=__int_as_float(d_MQ2i[bh]),mk2=__int_as_float(d_MK2i[bh]);
    float ext=sqrtf(fmaxf(mq2+mk2-n2,0.f));
    int ar=which?65:64;
    float* dst=which?d_kh:d_qh;
    float acc[4]={a0,a1,a2,a3};
    #pragma unroll
    for(int n=0;n<4;n++)
        dst[(n*BHn+bh)*Tn+t]=acc[n]+ext*sAl[ar*4+n]+sBe[n];
}

__global__ void k_sort(){
    __shared__ unsigned long long key[Tn];
    int bid=blockIdx.x,tid=threadIdx.x;   // 1024 threads
    int which=bid>>6, idx=bid&63;
    const float* hp=(which?d_kh:d_qh)+(size_t)idx*Tn;
    for(int i=tid;i<Tn;i+=1024){
        unsigned u=__float_as_uint(hp[i]);
        u=(u&0x80000000u)?~u:(u|0x80000000u);
        key[i]=((unsigned long long)u<<32)|(unsigned)i;
    }
    __syncthreads();
    for(int k2=2;k2<=Tn;k2<<=1)
        for(int j=k2>>1;j>0;j>>=1){
            for(int i=tid;i<Tn;i+=1024){
                int ixj=i^j;
                if(ixj>i){
                    unsigned long long a=key[i],b=key[ixj];
                    if((a>b)==((i&k2)==0)){ key[i]=b; key[ixj]=a; }
                }
            }
            __syncthreads();
        }
    int hsh=idx>>4,bh=idx&15;
    int* pdst=(which?d_kpos:d_qpos)+(size_t)idx*Tn;
    unsigned* cdst=which?d_kcode:d_qcode;
    for(int i=tid;i<Tn;i+=1024){
        int tok=(int)(key[i]&0xffffffffu);
        pdst[i]=tok;
        atomicOr(&cdst[bh*Tn+tok],(unsigned)(i>>7)<<(8*hsh));
    }
}

// ---- k features: FMA2 GEMM, logv -> d_kprime, block max ----
__global__ void __launch_bounds__(256) k_featmax(const float* __restrict__ x,
                                                 const float* __restrict__ proj){
    __shared__ float sX[64*33];
    __shared__ float sPT[32*258];
    __shared__ float sRed[256];
    int bx=blockIdx.x; int bh=bx>>6; int tile=bx&63; int t0=tile*64;
    int tid=threadIdx.x,ty=tid>>4,tx=tid&15;
    int b=bh>>3,h2=bh&7;
    unsigned long long acc2[4][8];
    #pragma unroll
    for(int u=0;u<4;u++)
        #pragma unroll
        for(int w=0;w<8;w++) acc2[u][w]=0ull;
    for(int ec=0;ec<2;ec++){
        __syncthreads();
        for(int i=tid;i<2048;i+=256){ int r=i>>5,e=i&31;
            sX[r*33+e]=x[((size_t)(b*Tn+t0+r)*8+h2)*64+ec*32+e]; }
        for(int i=tid;i<8192;i+=256){ int m=i>>5,e=i&31;
            sPT[e*258+m]=proj[m*64+ec*32+e]; }
        __syncthreads();
        #pragma unroll 4
        for(int e=0;e<32;e++){
            unsigned long long a2[4],b2[8];
            #pragma unroll
            for(int u=0;u<4;u++){ float av=sX[(u*16+ty)*33+e]; a2[u]=pk2(av,av); }
            #pragma unroll
            for(int w=0;w<8;w++) b2[w]=*(const unsigned long long*)&sPT[e*258+w*32+tx*2];
            #pragma unroll
            for(int u=0;u<4;u++)
                #pragma unroll
                for(int w=0;w<8;w++) FMA2(acc2[u][w],a2[u],b2[w],acc2[u][w]);
        }
    }
    float mx=-3.4e38f;
    #pragma unroll
    for(int u=0;u<4;u++){
        int row=u*16+ty;
        float dg=0.0625f*d_kn2[bh*Tn+t0+row];
        #pragma unroll
        for(int w=0;w<8;w++){
            float v0,v1; upk2(v0,v1,acc2[u][w]);
            float lv0=0.35355339059327373f*v0-dg;
            float lv1=0.35355339059327373f*v1-dg;
            mx=fmaxf(mx,fmaxf(lv0,lv1));
            *(float2*)&d_kprime[((size_t)bh*Tn+t0+row)*256+w*32+tx*2]=make_float2(lv0,lv1);
        }
    }
    sRed[tid]=mx; __syncthreads();
    for(int s=128;s;s>>=1){ if(tid<s) sRed[tid]=fmaxf(sRed[tid],sRed[tid+s]); __syncthreads(); }
    if(tid==0) atomicMax(&d_klsu[bh],fmap(sRed[0]));
}

// ---- kv = k'^T @ V (FMA2, fused exp+writeback+ksum) ----
__global__ void __launch_bounds__(256) k_kv(const float* __restrict__ v){
    __shared__ float sKP[32*65],sV[32*66];
    int split=blockIdx.x,mt=blockIdx.y,bh=blockIdx.z;
    int m0=mt*64,s0=split*512;
    int tid=threadIdx.x,ty=tid>>4,tx=tid&15;
    int b=bh>>3,h2=bh&7;
    float kls=funmap(d_klsu[bh]);
    unsigned long long acc2[4][2];
    #pragma unroll
    for(int u=0;u<4;u++){ acc2[u][0]=0ull; acc2[u][1]=0ull; }
    float ksp=0.f;
    for(int sb=0;sb<512;sb+=32){
        __syncthreads();
        for(int i=tid;i<2048;i+=256){ int r=i>>6,cc=i&63;
            size_t gi=((size_t)bh*Tn+s0+sb+r)*256+m0+cc;
            float lv=d_kprime[gi];
            float kp=__expf(lv-kls)*0.0625f;
            d_kprime[gi]=kp;
            sKP[r*65+cc]=kp;
            ksp+=kp;
            sV[r*66+cc]=v[((size_t)(b*Tn+s0+sb+r)*8+h2)*64+cc]; }
        __syncthreads();
        #pragma unroll 4
        for(int s=0;s<32;s++){
            unsigned long long a2[4],b2[2];
            #pragma unroll
            for(int u=0;u<4;u++){ float av=sKP[s*65+u*16+ty]; a2[u]=pk2(av,av); }
            b2[0]=*(const unsigned long long*)&sV[s*66+tx*2];
            b2[1]=*(const unsigned long long*)&sV[s*66+32+tx*2];
            #pragma unroll
            for(int u=0;u<4;u++){
                FMA2(acc2[u][0],a2[u],b2[0],acc2[u][0]);
                FMA2(acc2[u][1],a2[u],b2[1],acc2[u][1]);
            }
        }
    }
    atomicAdd(&d_ksum[bh*256+m0+(tid&63)],ksp);
    #pragma unroll
    for(int u=0;u<4;u++)
        #pragma unroll
        for(int w2=0;w2<2;w2++){
            float o0,o1; upk2(o0,o1,acc2[u][w2]);
            atomicAdd(&d_kvb[(bh*256+m0+u*16+ty)*64+w2*32+tx*2],o0);
            atomicAdd(&d_kvb[(bh*256+m0+u*16+ty)*64+w2*32+tx*2+1],o1);
        }
}

// ---- q features (FMA2): stab, pls, q', qk1 ----
__global__ void __launch_bounds__(256) k_qfeatg(const float* __restrict__ x,
                                                const float* __restrict__ proj){
    __shared__ float sX[64*33];
    __shared__ float sPT[32*258];
    __shared__ float sRed[64*17];
    __shared__ float sStab[64];
    __shared__ float sKsum[256];
    int bx=blockIdx.x; int bh=bx>>6; int tile=bx&63; int t0=tile*64;
    int tid=threadIdx.x,ty=tid>>4,tx=tid&15;
    int b=bh>>3,h2=bh&7;
    sKsum[tid]=d_ksum[bh*256+tid];
    unsigned long long acc2[4][8];
    #pragma unroll
    for(int u=0;u<4;u++)
        #pragma unroll
        for(int w=0;w<8;w++) acc2[u][w]=0ull;
    for(int ec=0;ec<2;ec++){
        __syncthreads();
        for(int i=tid;i<2048;i+=256){ int r=i>>5,e=i&31;
            sX[r*33+e]=x[((size_t)(b*Tn+t0+r)*8+h2)*64+ec*32+e]; }
        for(int i=tid;i<8192;i+=256){ int m=i>>5,e=i&31;
            sPT[e*258+m]=proj[m*64+ec*32+e]; }
        __syncthreads();
        #pragma unroll 4
        for(int e=0;e<32;e++){
            unsigned long long a2[4],b2[8];
            #pragma unroll
            for(int u=0;u<4;u++){ float av=sX[(u*16+ty)*33+e]; a2[u]=pk2(av,av); }
            #pragma unroll
            for(int w=0;w<8;w++) b2[w]=*(const unsigned long long*)&sPT[e*258+w*32+tx*2];
            #pragma unroll
            for(int u=0;u<4;u++)
                #pragma unroll
                for(int w=0;w<8;w++) FMA2(acc2[u][w],a2[u],b2[w],acc2[u][w]);
        }
    }
    float kls=funmap(d_klsu[bh]);
    #pragma unroll
    for(int u=0;u<4;u++){
        int row=u*16+ty;
        float dg=0.0625f*d_qn2[bh*Tn+t0+row];
        float rm=-3.4e38f;
        #pragma unroll
        for(int w=0;w<8;w++){
            float v0,v1; upk2(v0,v1,acc2[u][w]);
            float lv0=0.35355339059327373f*v0-dg;
            float lv1=0.35355339059327373f*v1-dg;
            rm=fmaxf(rm,fmaxf(lv0,lv1));
            acc2[u][w]=pk2(lv0,lv1);
        }
        sRed[row*17+tx]=rm;
    }
    __syncthreads();
    if(tid<64){
        float m=sRed[tid*17];
        #pragma unroll
        for(int c=1;c<16;c++) m=fmaxf(m,sRed[tid*17+c]);
        sStab[tid]=m;
        d_pls[bh*Tn+t0+tid]=m+kls;
    }
    __syncthreads();
    float part[4]={};
    #pragma unroll
    for(int u=0;u<4;u++){
        int row=u*16+ty;
        float st=sStab[row];
        #pragma unroll
        for(int w=0;w<8;w++){
            float lv0,lv1; upk2(lv0,lv1,acc2[u][w]);
            float qp0=__expf(lv0-st)*0.0625f;
            float qp1=__expf(lv1-st)*0.0625f;
            *(float2*)&d_qprime[((size_t)bh*Tn+t0+row)*256+w*32+tx*2]=make_float2(qp0,qp1);
            part[u]=fmaf(qp0,sKsum[w*32+tx*2],part[u]);
            part[u]=fmaf(qp1,sKsum[w*32+tx*2+1],part[u]);
        }
    }
    __syncthreads();
    #pragma unroll
    for(int u=0;u<4;u++) sRed[(u*16+ty)*17+tx]=part[u];
    __syncthreads();
    if(tid<64){
        float s=0.f;
        #pragma unroll
        for(int c=0;c<16;c++) s+=sRed[tid*17+c];
        d_qk1[bh*Tn+t0+tid]=s;
    }
}

// ---- qkv = q' @ kv (FMA2) ----
__global__ void __launch_bounds__(256) k_qkv(){
    __shared__ float sQ[64*33],sKV[32*66];
    int tile=blockIdx.x,bh=blockIdx.y,t0=tile*64;
    int tid=threadIdx.x,ty=tid>>4,tx=tid&15;
    unsigned long long acc2[4][2];
    #pragma unroll
    for(int u=0;u<4;u++){ acc2[u][0]=0ull; acc2[u][1]=0ull; }
    for(int c=0;c<8;c++){
        __syncthreads();
        for(int i=tid;i<2048;i+=256){ int r=i>>5,m=i&31;
            sQ[r*33+m]=d_qprime[((size_t)bh*Tn+t0+r)*256+c*32+m]; }
        for(int i=tid;i<2048;i+=256){ int m=i>>6,dd=i&63;
            sKV[m*66+dd]=d_kvb[(bh*256+c*32+m)*64+dd]; }
        __syncthreads();
        #pragma unroll 4
        for(int m=0;m<32;m++){
            unsigned long long a2[4],b2[2];
            #pragma unroll
            for(int u=0;u<4;u++){ float av=sQ[(u*16+ty)*33+m]; a2[u]=pk2(av,av); }
            b2[0]=*(const unsigned long long*)&sKV[m*66+tx*2];
            b2[1]=*(const unsigned long long*)&sKV[m*66+32+tx*2];
            #pragma unroll
            for(int u=0;u<4;u++){
                FMA2(acc2[u][0],a2[u],b2[0],acc2[u][0]);
                FMA2(acc2[u][1],a2[u],b2[1],acc2[u][1]);
            }
        }
    }
    #pragma unroll
    for(int u=0;u<4;u++)
        #pragma unroll
        for(int w2=0;w2<2;w2++){
            float o0,o1; upk2(o0,o1,acc2[u][w2]);
            *(float2*)&d_qkv[((size_t)bh*Tn+t0+u*16+ty)*64+w2*32+tx*2]=make_float2(o0,o1);
        }
}

// dyn smem floats: sInner 16512 | A0 4352 | BT0 4224 | A1 4352 | BT1 4224 | meta 896
#define S_A0 16512
#define S_BT0 20864
#define S_A1 25088
#define S_BT1 29312
#define S_META 33536
#define ATTN_SMEM_BYTES ((S_META+896)*4)

__global__ void __launch_bounds__(512,1) k_attn(const float* __restrict__ q,
                                                const float* __restrict__ k,
                                                const float* __restrict__ v){
    extern __shared__ float dyn[];
    float* sInner=dyn;
    int* sQt=(int*)(dyn+S_META);
    int* sKt=(int*)(dyn+S_META+128);
    unsigned* sQC=(unsigned*)(dyn+S_META+256);
    unsigned* sKC=(unsigned*)(dyn+S_META+384);
    float* sPls=dyn+S_META+512;
    float* sLse=dyn+S_META+640;
    float* sPexp=dyn+S_META+768;
    int n=blockIdx.x,bh=blockIdx.y,h=blockIdx.z;
    int b=bh>>3,h2=bh&7,hb=h*BHn+bh;
    int tid=threadIdx.x,ty=tid>>4,tx=tid&15;
    if(tid<128){
        int qt=d_qpos[(size_t)hb*Tn+n*128+tid];
        int kt=d_kpos[(size_t)hb*Tn+n*128+tid];
        sQt[tid]=qt; sKt[tid]=kt;
        sQC[tid]=d_qcode[bh*Tn+qt]; sKC[tid]=d_kcode[bh*Tn+kt];
        sPls[tid]=d_pls[bh*Tn+qt];
    }
    __syncthreads();
    unsigned long long accI[4][4];
    #pragma unroll
    for(int u=0;u<4;u++)
        #pragma unroll
        for(int w=0;w<4;w++) accI[u][w]=0ull;
    float4 qa[2],ka[2];
    #pragma unroll
    for(int j2=0;j2<2;j2++){
        int idx=tid+j2*512; int r=idx>>3,seg=idx&7;
        qa[j2]=*(const float4*)&q[((size_t)(b*Tn+sQt[r])*8+h2)*64+seg*4];
        ka[j2]=*(const float4*)&k[((size_t)(b*Tn+sKt[r])*8+h2)*64+seg*4];
    }
    {
        float* sA=dyn+S_A0; float* sBT=dyn+S_BT0;
        #pragma unroll
        for(int j2=0;j2<2;j2++){
            int idx=tid+j2*512; int r=idx>>3,seg=idx&7;
            sA[r*33+seg*4+0]=qa[j2].x; sA[r*33+seg*4+1]=qa[j2].y;
            sA[r*33+seg*4+2]=qa[j2].z; sA[r*33+seg*4+3]=qa[j2].w;
            sBT[(seg*4+0)*130+r]=ka[j2].x; sBT[(seg*4+1)*130+r]=ka[j2].y;
            sBT[(seg*4+2)*130+r]=ka[j2].z; sBT[(seg*4+3)*130+r]=ka[j2].w;
        }
    }
    #pragma unroll
    for(int j2=0;j2<2;j2++){
        int idx=tid+j2*512; int r=idx>>3,seg=idx&7;
        qa[j2]=*(const float4*)&q[((size_t)(b*Tn+sQt[r])*8+h2)*64+32+seg*4];
        ka[j2]=*(const float4*)&k[((size_t)(b*Tn+sKt[r])*8+h2)*64+32+seg*4];
    }
    __syncthreads();
    for(int ec=0;ec<2;ec++){
        float* sA=dyn+(ec?S_A1:S_A0); float* sBT=dyn+(ec?S_BT1:S_BT0);
        #pragma unroll 4
        for(int e=0;e<32;e++){
            unsigned long long a2[4],b2[4];
            #pragma unroll
            for(int u=0;u<4;u++){ float av=sA[(u*32+ty)*33+e]; a2[u]=pk2(av,av); }
            #pragma unroll
            for(int w=0;w<4;w++) b2[w]=*(const unsigned long long*)&sBT[e*130+w*32+tx*2];
            #pragma unroll
            for(int u=0;u<4;u++)
                #pragma unroll
                for(int w=0;w<4;w++) FMA2(accI[u][w],a2[u],b2[w],accI[u][w]);
        }
        if(ec==0){
            float* sA1=dyn+S_A1; float* sBT1=dyn+S_BT1;
            #pragma unroll
            for(int j2=0;j2<2;j2++){
                int idx=tid+j2*512; int r=idx>>3,seg=idx&7;
                sA1[r*33+seg*4+0]=qa[j2].x; sA1[r*33+seg*4+1]=qa[j2].y;
                sA1[r*33+seg*4+2]=qa[j2].z; sA1[r*33+seg*4+3]=qa[j2].w;
                sBT1[(seg*4+0)*130+r]=ka[j2].x; sBT1[(seg*4+1)*130+r]=ka[j2].y;
                sBT1[(seg*4+2)*130+r]=ka[j2].z; sBT1[(seg*4+3)*130+r]=ka[j2].w;
            }
            __syncthreads();
        }
    }
    const float ldt[4]={0.f,0.6931471805599453f,1.0986122886681098f,1.3862943611198906f};
    #pragma unroll
    for(int u=0;u<4;u++){
        int i=u*32+ty;
        unsigned qc=sQC[i];
        float rm=-3.4e38f;
        #pragma unroll
        for(int w=0;w<4;w++){
            int j0=w*32+tx*2;
            float v0,v1; upk2(v0,v1,accI[u][w]);
            int dup0=__popc(__vcmpeq4(qc,sKC[j0]))>>3;
            int dup1=__popc(__vcmpeq4(qc,sKC[j0+1]))>>3;
            float val0=v0*0.125f-ldt[dup0-1];
            float val1=v1*0.125f-ldt[dup1-1];
            sInner[i*129+j0]=val0; sInner[i*129+j0+1]=val1;
            rm=fmaxf(rm,fmaxf(val0,val1));
        }
        #pragma unroll
        for(int o=8;o;o>>=1) rm=fmaxf(rm,__shfl_xor_sync(0xffffffffu,rm,o,16));
        if(tx==0){
            float l=fmaxf(rm,sPls[i]);
            sLse[i]=l; sPexp[i]=__expf(sPls[i]-l);
        }
    }
    unsigned long long accP[4][4];
    #pragma unroll
    for(int u=0;u<4;u++)
        #pragma unroll
        for(int w=0;w<4;w++) accP[u][w]=0ull;
    float4 pa[2],pb[2];
    #pragma unroll
    for(int j2=0;j2<2;j2++){
        int idx=tid+j2*512; int r=idx>>3,seg=idx&7;
        pa[j2]=*(const float4*)&d_qprime[((size_t)bh*Tn+sQt[r])*256+seg*4];
        pb[j2]=*(const float4*)&d_kprime[((size_t)bh*Tn+sKt[r])*256+seg*4];
    }
    {
        float* sA=dyn+S_A0; float* sBT=dyn+S_BT0;
        #pragma unroll
        for(int j2=0;j2<2;j2++){
            int idx=tid+j2*512; int r=idx>>3,seg=idx&7;
            sA[r*33+seg*4+0]=pa[j2].x; sA[r*33+seg*4+1]=pa[j2].y;
            sA[r*33+seg*4+2]=pa[j2].z; sA[r*33+seg*4+3]=pa[j2].w;
            sBT[(seg*4+0)*130+r]=pb[j2].x; sBT[(seg*4+1)*130+r]=pb[j2].y;
            sBT[(seg*4+2)*130+r]=pb[j2].z; sBT[(seg*4+3)*130+r]=pb[j2].w;
        }
    }
    #pragma unroll
    for(int j2=0;j2<2;j2++){
        int idx=tid+j2*512; int r=idx>>3,seg=idx&7;
        pa[j2]=*(const float4*)&d_qprime[((size_t)bh*Tn+sQt[r])*256+32+seg*4];
        pb[j2]=*(const float4*)&d_kprime[((size_t)bh*Tn+sKt[r])*256+32+seg*4];
    }
    __syncthreads();
    for(int c=0;c<8;c++){
        if(c<7){
            float* sA=dyn+(((c+1)&1)?S_A1:S_A0); float* sBT=dyn+(((c+1)&1)?S_BT1:S_BT0);
            #pragma unroll
            for(int j2=0;j2<2;j2++){
                int idx=tid+j2*512; int r=idx>>3,seg=idx&7;
                sA[r*33+seg*4+0]=pa[j2].x; sA[r*33+seg*4+1]=pa[j2].y;
                sA[r*33+seg*4+2]=pa[j2].z; sA[r*33+seg*4+3]=pa[j2].w;
                sBT[(seg*4+0)*130+r]=pb[j2].x; sBT[(seg*4+1)*130+r]=pb[j2].y;
                sBT[(seg*4+2)*130+r]=pb[j2].z; sBT[(seg*4+3)*130+r]=pb[j2].w;
            }
            if(c<6){
                #pragma unroll
                for(int j2=0;j2<2;j2++){
                    int idx=tid+j2*512; int r=idx>>3,seg=idx&7;
                    pa[j2]=*(const float4*)&d_qprime[((size_t)bh*Tn+sQt[r])*256+(c+2)*32+seg*4];
                    pb[j2]=*(const float4*)&d_kprime[((size_t)bh*Tn+sKt[r])*256+(c+2)*32+seg*4];
                }
            }
        }
        float* sA=dyn+((c&1)?S_A1:S_A0); float* sBT=dyn+((c&1)?S_BT1:S_BT0);
        #pragma unroll 4
        for(int m=0;m<32;m++){
            unsigned long long a2[4],b2[4];
            #pragma unroll
            for(int u=0;u<4;u++){ float av=sA[(u*32+ty)*33+m]; a2[u]=pk2(av,av); }
            #pragma unroll
            for(int w=0;w<4;w++) b2[w]=*(const unsigned long long*)&sBT[m*130+w*32+tx*2];
            #pragma unroll
            for(int u=0;u<4;u++)
                #pragma unroll
                for(int w=0;w<4;w++) FMA2(accP[u][w],a2[u],b2[w],accP[u][w]);
        }
        __syncthreads();
    }
    float* sDots=dyn+S_A0;
    float* sV=dyn+S_BT0;
    unsigned long long accO[4][2];
    #pragma unroll
    for(int u=0;u<4;u++){ accO[u][0]=0ull; accO[u][1]=0ull; }
    float rsum[4]={};
    for(int jc=0;jc<4;jc++){
        if(jc) __syncthreads();
        #pragma unroll
        for(int u=0;u<4;u++){
            int i=u*32+ty;
            float lse=sLse[i],pe=sPexp[i];
            unsigned qc=sQC[i];
            int j0=jc*32+tx*2;
            float p0,p1; upk2(p0,p1,accP[u][jc]);
            int dup0=__popc(__vcmpeq4(qc,sKC[j0]))>>3;
            int dup1=__popc(__vcmpeq4(qc,sKC[j0+1]))>>3;
            float dots0=__expf(sInner[i*129+j0]-lse)-(p0/(float)dup0)*pe;
            float dots1=__expf(sInner[i*129+j0+1]-lse)-(p1/(float)dup1)*pe;
            rsum[u]+=dots0+dots1;
            *(float2*)&sDots[i*34+tx*2]=make_float2(dots0,dots1);
        }
        {
            int jj=tid>>4, seg=tid&15;
            float4 va=*(const float4*)&v[((size_t)(b*Tn+sKt[jc*32+jj])*8+h2)*64+seg*4];
            *(float2*)&sV[jj*66+seg*4]=make_float2(va.x,va.y);
            *(float2*)&sV[jj*66+seg*4+2]=make_float2(va.z,va.w);
        }
        __syncthreads();
        #pragma unroll 4
        for(int jj=0;jj<32;jj++){
            unsigned long long dv2[4],vv2[2];
            #pragma unroll
            for(int u=0;u<4;u++){ float dvv=sDots[(u*32+ty)*34+jj]; dv2[u]=pk2(dvv,dvv); }
            vv2[0]=*(const unsigned long long*)&sV[jj*66+tx*2];
            vv2[1]=*(const unsigned long long*)&sV[jj*66+32+tx*2];
            #pragma unroll
            for(int u=0;u<4;u++){
                FMA2(accO[u][0],dv2[u],vv2[0],accO[u][0]);
                FMA2(accO[u][1],dv2[u],vv2[1],accO[u][1]);
            }
        }
    }
    #pragma unroll
    for(int u=0;u<4;u++){
        int i=u*32+ty;
        int qt=sQt[i];
        float rs=rsum[u];
        #pragma unroll
        for(int o=8;o;o>>=1) rs+=__shfl_xor_sync(0xffffffffu,rs,o,16);
        if(tx==0){
            d_logits[(size_t)hb*Tn+qt]=sLse[i];
            d_dsumg[(size_t)hb*Tn+qt]=rs;
        }
        #pragma unroll
        for(int w2=0;w2<2;w2++){
            float o0,o1; upk2(o0,o1,accO[u][w2]);
            *(float2*)&d_obuf[((size_t)hb*Tn+qt)*64+w2*32+tx*2]=make_float2(o0,o1);
        }
    }
}

__global__ void k_final(float* __restrict__ out){
    int gid=blockIdx.x*256+threadIdx.x;
    int bh=gid>>14,rr=gid&16383,t=rr>>2,gq=rr&3;
    int g=bh*Tn+t;
    float l[4],ds[4];
    #pragma unroll
    for(int h=0;h<4;h++){ l[h]=d_logits[(size_t)(h*BHn+bh)*Tn+t]; ds[h]=d_dsumg[(size_t)(h*BHn+bh)*Tn+t]; }
    float m=fmaxf(fmaxf(l[0],l[1]),fmaxf(l[2],l[3]));
    float s=__expf(l[0]-m)+__expf(l[1]-m)+__expf(l[2]-m)+__expf(l[3]-m);
    float nls=m+__logf(s);
    float ps=__expf(d_pls[g]-nls);
    float p[4];
    float norm=d_qk1[g]*ps;
    #pragma unroll
    for(int h=0;h<4;h++){ p[h]=__expf(l[h]-nls); norm=fmaf(ds[h],p[h],norm); }
    norm=fmaxf(norm,1e-6f);
    float inv=1.f/norm;
    int b=bh>>3,h2=bh&7;
    const float4* qkv4=(const float4*)(d_qkv+(size_t)g*64+gq*16);
    float4* o4=(float4*)(out+((size_t)(b*Tn+t)*8+h2)*64+gq*16);
    #pragma unroll
    for(int j=0;j<4;j++){
        float4 a=qkv4[j];
        float4 r; r.x=a.x*ps; r.y=a.y*ps; r.z=a.z*ps; r.w=a.w*ps;
        #pragma unroll
        for(int h=0;h<4;h++){
            const float4 ob=((const float4*)(d_obuf+((size_t)(h*BHn+bh)*Tn+t)*64+gq*16))[j];
            r.x=fmaf(ob.x,p[h],r.x); r.y=fmaf(ob.y,p[h],r.y);
            r.z=fmaf(ob.z,p[h],r.z); r.w=fmaf(ob.w,p[h],r.w);
        }
        r.x*=inv; r.y*=inv; r.z*=inv; r.w*=inv;
        o4[j]=r;
    }
}

extern "C" void kernel_launch(void* const* d_in, const int* in_sizes, int n_in,
                              void* d_out, int out_size){
    const float* q=(const float*)d_in[0];
    const float* k=(const float*)d_in[1];
    const float* v=(const float*)d_in[2];
    const float* proj=(const float*)d_in[3];
    const float* alpha=(const float*)d_in[4];
    const float* beta=(const float*)d_in[5];
    float* out=(float*)d_out;
    cudaFuncSetAttribute(k_attn, cudaFuncAttributeMaxDynamicSharedMemorySize, ATTN_SMEM_BYTES);
    k_init<<<1024,256>>>();
    k_norms<<<256,256>>>(q,k);
    k_hash<<<512,256>>>(q,k,alpha,beta);
    k_sort<<<128,1024>>>();
    k_featmax<<<1024,256>>>(k,proj);
    k_kv<<<dim3(8,4,16),256>>>(v);
    k_qfeatg<<<1024,256>>>(q,proj);
    k_qkv<<<dim3(64,16),256>>>();
    k_attn<<<dim3(32,16,4),512,ATTN_SMEM_BYTES>>>(q,k,v);
    k_final<<<1024,256>>>(out);
}

// round 15
// speedup vs baseline: 1.0495x; 1.0205x over previous
#include <cuda_runtime.h>
#include <cstdint>

#define Tn 4096
#define BHn 16
#define BHT 65536

__device__ float    d_qn2[BHT];
__device__ float    d_kn2[BHT];
__device__ int      d_MQ2i[BHn];
__device__ int      d_MK2i[BHn];
__device__ unsigned d_klsu[BHn];
__device__ float    d_qh[4*BHT];
__device__ float    d_kh[4*BHT];
__device__ int      d_qpos[4*BHT];
__device__ int      d_kpos[4*BHT];
__device__ unsigned d_qcode[BHT];
__device__ unsigned d_kcode[BHT];
__device__ float    d_kprime[16777216];
__device__ float    d_qprime[16777216];
__device__ float    d_ksum[BHn*256];
__device__ float    d_kvb[BHn*256*64];
__device__ float    d_qk1[BHT];
__device__ float    d_pls[BHT];
__device__ float    d_qkv[BHT*64];
__device__ float    d_obuf[4ll*BHT*64];
__device__ float    d_logits[4*BHT];
__device__ float    d_dsumg[4*BHT];

__device__ __forceinline__ unsigned fmap(float f){
    unsigned u=__float_as_uint(f); return (u&0x80000000u)?~u:(u|0x80000000u);
}
__device__ __forceinline__ float funmap(unsigned u){
    return (u&0x80000000u)?__uint_as_float(u&0x7FFFFFFFu):__uint_as_float(~u);
}
__device__ __forceinline__ unsigned long long pk2(float x,float y){
    unsigned long long r; asm("mov.b64 %0,{%1,%2};":"=l"(r):"f"(x),"f"(y)); return r;
}
__device__ __forceinline__ void upk2(float&x,float&y,unsigned long long v){
    asm("mov.b64 {%0,%1},%2;":"=f"(x),"=f"(y):"l"(v));
}
#define FMA2(d,a,b,c) asm("fma.rn.f32x2 %0,%1,%2,%3;":"=l"(d):"l"(a),"l"(b),"l"(c))

__global__ void k_init(){
    int i=blockIdx.x*256+threadIdx.x;
    if(i<16){ d_MQ2i[i]=0; d_MK2i[i]=0; d_klsu[i]=0u; }
    if(i<BHT){ d_qcode[i]=0u; d_kcode[i]=0u; }
    if(i<4096) d_ksum[i]=0.f;
    if(i<262144) d_kvb[i]=0.f;
}

__global__ void k_norms(const float* __restrict__ q,const float* __restrict__ k){
    int g=blockIdx.x*256+threadIdx.x;
    int bh=g>>12,t=g&4095,b=bh>>3,h2=bh&7;
    const float4* qp=(const float4*)(q+((size_t)(b*Tn+t)*8+h2)*64);
    const float4* kp=(const float4*)(k+((size_t)(b*Tn+t)*8+h2)*64);
    float sq=0.f,sk=0.f;
    #pragma unroll
    for(int i=0;i<16;i++){
        float4 a=qp[i]; sq+=a.x*a.x+a.y*a.y+a.z*a.z+a.w*a.w;
        float4 c=kp[i]; sk+=c.x*c.x+c.y*c.y+c.z*c.z+c.w*c.w;
    }
    d_qn2[g]=sq; d_kn2[g]=sk;
    atomicMax(&d_MQ2i[bh],__float_as_int(sq));
    atomicMax(&d_MK2i[bh],__float_as_int(sk));
}

__global__ void k_hash(const float* __restrict__ q,const float* __restrict__ k,
                       const float* __restrict__ alpha,const float* __restrict__ beta){
    __shared__ float sAl[264],sBe[4];
    int tid=threadIdx.x;
    for(int i=tid;i<264;i+=256) sAl[i]=alpha[i];
    if(tid<4) sBe[tid]=beta[tid];
    __syncthreads();
    int gid=blockIdx.x*256+tid;
    int which=gid>>16, g=gid&65535;
    int bh=g>>12,t=g&4095,b=bh>>3,h2=bh&7;
    const float* base=which?k:q;
    const float4* row=(const float4*)(base+((size_t)(b*Tn+t)*8+h2)*64);
    float a0=0,a1=0,a2=0,a3=0;
    #pragma unroll
    for(int j=0;j<16;j++){
        float4 v=row[j]; int e=j*4;
        a0=fmaf(v.x,sAl[e*4+0],a0);a1=fmaf(v.x,sAl[e*4+1],a1);a2=fmaf(v.x,sAl[e*4+2],a2);a3=fmaf(v.x,sAl[e*4+3],a3);
        a0=fmaf(v.y,sAl[e*4+4],a0);a1=fmaf(v.y,sAl[e*4+5],a1);a2=fmaf(v.y,sAl[e*4+6],a2);a3=fmaf(v.y,sAl[e*4+7],a3);
        a0=fmaf(v.z,sAl[e*4+8],a0);a1=fmaf(v.z,sAl[e*4+9],a1);a2=fmaf(v.z,sAl[e*4+10],a2);a3=fmaf(v.z,sAl[e*4+11],a3);
        a0=fmaf(v.w,sAl[e*4+12],a0);a1=fmaf(v.w,sAl[e*4+13],a1);a2=fmaf(v.w,sAl[e*4+14],a2);a3=fmaf(v.w,sAl[e*4+15],a3);
    }
    float n2=which?d_kn2[g]:d_qn2[g];
    float mq2=__int_as_float(d_MQ2i[bh]),mk2=__int_as_float(d_MK2i[bh]);
    float ext=sqrtf(fmaxf(mq2+mk2-n2,0.f));
    int ar=which?65:64;
    float* dst=which?d_kh:d_qh;
    float acc[4]={a0,a1,a2,a3};
    #pragma unroll
    for(int n=0;n<4;n++)
        dst[(n*BHn+bh)*Tn+t]=acc[n]+ext*sAl[ar*4+n]+sBe[n];
}

__global__ void k_sort(){
    __shared__ unsigned long long key[Tn];
    int bid=blockIdx.x,tid=threadIdx.x;
    int which=bid>>6, idx=bid&63;
    const float* hp=(which?d_kh:d_qh)+(size_t)idx*Tn;
    for(int i=tid;i<Tn;i+=1024){
        unsigned u=__float_as_uint(hp[i]);
        u=(u&0x80000000u)?~u:(u|0x80000000u);
        key[i]=((unsigned long long)u<<32)|(unsigned)i;
    }
    __syncthreads();
    for(int k2=2;k2<=Tn;k2<<=1)
        for(int j=k2>>1;j>0;j>>=1){
            for(int i=tid;i<Tn;i+=1024){
                int ixj=i^j;
                if(ixj>i){
                    unsigned long long a=key[i],b=key[ixj];
                    if((a>b)==((i&k2)==0)){ key[i]=b; key[ixj]=a; }
                }
            }
            __syncthreads();
        }
    int hsh=idx>>4,bh=idx&15;
    int* pdst=(which?d_kpos:d_qpos)+(size_t)idx*Tn;
    unsigned* cdst=which?d_kcode:d_qcode;
    for(int i=tid;i<Tn;i+=1024){
        int tok=(int)(key[i]&0xffffffffu);
        pdst[i]=tok;
        atomicOr(&cdst[bh*Tn+tok],(unsigned)(i>>7)<<(8*hsh));
    }
}

__global__ void __launch_bounds__(256) k_featmax(const float* __restrict__ x,
                                                 const float* __restrict__ proj){
    __shared__ float sX[64*33];
    __shared__ float sPT[32*258];
    __shared__ float sRed[256];
    int bx=blockIdx.x; int bh=bx>>6; int tile=bx&63; int t0=tile*64;
    int tid=threadIdx.x,ty=tid>>4,tx=tid&15;
    int b=bh>>3,h2=bh&7;
    unsigned long long acc2[4][8];
    #pragma unroll
    for(int u=0;u<4;u++)
        #pragma unroll
        for(int w=0;w<8;w++) acc2[u][w]=0ull;
    for(int ec=0;ec<2;ec++){
        __syncthreads();
        for(int i=tid;i<2048;i+=256){ int r=i>>5,e=i&31;
            sX[r*33+e]=x[((size_t)(b*Tn+t0+r)*8+h2)*64+ec*32+e]; }
        for(int i=tid;i<8192;i+=256){ int m=i>>5,e=i&31;
            sPT[e*258+m]=proj[m*64+ec*32+e]; }
        __syncthreads();
        #pragma unroll 4
        for(int e=0;e<32;e++){
            unsigned long long a2[4],b2[8];
            #pragma unroll
            for(int u=0;u<4;u++){ float av=sX[(u*16+ty)*33+e]; a2[u]=pk2(av,av); }
            #pragma unroll
            for(int w=0;w<8;w++) b2[w]=*(const unsigned long long*)&sPT[e*258+w*32+tx*2];
            #pragma unroll
            for(int u=0;u<4;u++)
                #pragma unroll
                for(int w=0;w<8;w++) FMA2(acc2[u][w],a2[u],b2[w],acc2[u][w]);
        }
    }
    float mx=-3.4e38f;
    #pragma unroll
    for(int u=0;u<4;u++){
        int row=u*16+ty;
        float dg=0.0625f*d_kn2[bh*Tn+t0+row];
        #pragma unroll
        for(int w=0;w<8;w++){
            float v0,v1; upk2(v0,v1,acc2[u][w]);
            float lv0=0.35355339059327373f*v0-dg;
            float lv1=0.35355339059327373f*v1-dg;
            mx=fmaxf(mx,fmaxf(lv0,lv1));
            *(float2*)&d_kprime[((size_t)bh*Tn+t0+row)*256+w*32+tx*2]=make_float2(lv0,lv1);
        }
    }
    sRed[tid]=mx; __syncthreads();
    for(int s=128;s;s>>=1){ if(tid<s) sRed[tid]=fmaxf(sRed[tid],sRed[tid+s]); __syncthreads(); }
    if(tid==0) atomicMax(&d_klsu[bh],fmap(sRed[0]));
}

__global__ void __launch_bounds__(256) k_kv(const float* __restrict__ v){
    __shared__ float sKP[32*65],sV[32*66];
    int split=blockIdx.x,mt=blockIdx.y,bh=blockIdx.z;
    int m0=mt*64,s0=split*512;
    int tid=threadIdx.x,ty=tid>>4,tx=tid&15;
    int b=bh>>3,h2=bh&7;
    float kls=funmap(d_klsu[bh]);
    unsigned long long acc2[4][2];
    #pragma unroll
    for(int u=0;u<4;u++){ acc2[u][0]=0ull; acc2[u][1]=0ull; }
    float ksp=0.f;
    for(int sb=0;sb<512;sb+=32){
        __syncthreads();
        for(int i=tid;i<2048;i+=256){ int r=i>>6,cc=i&63;
            size_t gi=((size_t)bh*Tn+s0+sb+r)*256+m0+cc;
            float lv=d_kprime[gi];
            float kp=__expf(lv-kls)*0.0625f;
            d_kprime[gi]=kp;
            sKP[r*65+cc]=kp;
            ksp+=kp;
            sV[r*66+cc]=v[((size_t)(b*Tn+s0+sb+r)*8+h2)*64+cc]; }
        __syncthreads();
        #pragma unroll 4
        for(int s=0;s<32;s++){
            unsigned long long a2[4],b2[2];
            #pragma unroll
            for(int u=0;u<4;u++){ float av=sKP[s*65+u*16+ty]; a2[u]=pk2(av,av); }
            b2[0]=*(const unsigned long long*)&sV[s*66+tx*2];
            b2[1]=*(const unsigned long long*)&sV[s*66+32+tx*2];
            #pragma unroll
            for(int u=0;u<4;u++){
                FMA2(acc2[u][0],a2[u],b2[0],acc2[u][0]);
                FMA2(acc2[u][1],a2[u],b2[1],acc2[u][1]);
            }
        }
    }
    atomicAdd(&d_ksum[bh*256+m0+(tid&63)],ksp);
    #pragma unroll
    for(int u=0;u<4;u++)
        #pragma unroll
        for(int w2=0;w2<2;w2++){
            float o0,o1; upk2(o0,o1,acc2[u][w2]);
            atomicAdd(&d_kvb[(bh*256+m0+u*16+ty)*64+w2*32+tx*2],o0);
            atomicAdd(&d_kvb[(bh*256+m0+u*16+ty)*64+w2*32+tx*2+1],o1);
        }
}

__global__ void __launch_bounds__(256) k_qfeatg(const float* __restrict__ x,
                                                const float* __restrict__ proj){
    __shared__ float sX[64*33];
    __shared__ float sPT[32*258];
    __shared__ float sRed[64*17];
    __shared__ float sStab[64];
    __shared__ float sKsum[256];
    int bx=blockIdx.x; int bh=bx>>6; int tile=bx&63; int t0=tile*64;
    int tid=threadIdx.x,ty=tid>>4,tx=tid&15;
    int b=bh>>3,h2=bh&7;
    sKsum[tid]=d_ksum[bh*256+tid];
    unsigned long long acc2[4][8];
    #pragma unroll
    for(int u=0;u<4;u++)
        #pragma unroll
        for(int w=0;w<8;w++) acc2[u][w]=0ull;
    for(int ec=0;ec<2;ec++){
        __syncthreads();
        for(int i=tid;i<2048;i+=256){ int r=i>>5,e=i&31;
            sX[r*33+e]=x[((size_t)(b*Tn+t0+r)*8+h2)*64+ec*32+e]; }
        for(int i=tid;i<8192;i+=256){ int m=i>>5,e=i&31;
            sPT[e*258+m]=proj[m*64+ec*32+e]; }
        __syncthreads();
        #pragma unroll 4
        for(int e=0;e<32;e++){
            unsigned long long a2[4],b2[8];
            #pragma unroll
            for(int u=0;u<4;u++){ float av=sX[(u*16+ty)*33+e]; a2[u]=pk2(av,av); }
            #pragma unroll
            for(int w=0;w<8;w++) b2[w]=*(const unsigned long long*)&sPT[e*258+w*32+tx*2];
            #pragma unroll
            for(int u=0;u<4;u++)
                #pragma unroll
                for(int w=0;w<8;w++) FMA2(acc2[u][w],a2[u],b2[w],acc2[u][w]);
        }
    }
    float kls=funmap(d_klsu[bh]);
    #pragma unroll
    for(int u=0;u<4;u++){
        int row=u*16+ty;
        float dg=0.0625f*d_qn2[bh*Tn+t0+row];
        float rm=-3.4e38f;
        #pragma unroll
        for(int w=0;w<8;w++){
            float v0,v1; upk2(v0,v1,acc2[u][w]);
            float lv0=0.35355339059327373f*v0-dg;
            float lv1=0.35355339059327373f*v1-dg;
            rm=fmaxf(rm,fmaxf(lv0,lv1));
            acc2[u][w]=pk2(lv0,lv1);
        }
        sRed[row*17+tx]=rm;
    }
    __syncthreads();
    if(tid<64){
        float m=sRed[tid*17];
        #pragma unroll
        for(int c=1;c<16;c++) m=fmaxf(m,sRed[tid*17+c]);
        sStab[tid]=m;
        d_pls[bh*Tn+t0+tid]=m+kls;
    }
    __syncthreads();
    float part[4]={};
    #pragma unroll
    for(int u=0;u<4;u++){
        int row=u*16+ty;
        float st=sStab[row];
        #pragma unroll
        for(int w=0;w<8;w++){
            float lv0,lv1; upk2(lv0,lv1,acc2[u][w]);
            float qp0=__expf(lv0-st)*0.0625f;
            float qp1=__expf(lv1-st)*0.0625f;
            *(float2*)&d_qprime[((size_t)bh*Tn+t0+row)*256+w*32+tx*2]=make_float2(qp0,qp1);
            part[u]=fmaf(qp0,sKsum[w*32+tx*2],part[u]);
            part[u]=fmaf(qp1,sKsum[w*32+tx*2+1],part[u]);
        }
    }
    __syncthreads();
    #pragma unroll
    for(int u=0;u<4;u++) sRed[(u*16+ty)*17+tx]=part[u];
    __syncthreads();
    if(tid<64){
        float s=0.f;
        #pragma unroll
        for(int c=0;c<16;c++) s+=sRed[tid*17+c];
        d_qk1[bh*Tn+t0+tid]=s;
    }
}

__global__ void __launch_bounds__(256) k_qkv(){
    __shared__ float sQ[64*33],sKV[32*66];
    int tile=blockIdx.x,bh=blockIdx.y,t0=tile*64;
    int tid=threadIdx.x,ty=tid>>4,tx=tid&15;
    unsigned long long acc2[4][2];
    #pragma unroll
    for(int u=0;u<4;u++){ acc2[u][0]=0ull; acc2[u][1]=0ull; }
    for(int c=0;c<8;c++){
        __syncthreads();
        for(int i=tid;i<2048;i+=256){ int r=i>>5,m=i&31;
            sQ[r*33+m]=d_qprime[((size_t)bh*Tn+t0+r)*256+c*32+m]; }
        for(int i=tid;i<2048;i+=256){ int m=i>>6,dd=i&63;
            sKV[m*66+dd]=d_kvb[(bh*256+c*32+m)*64+dd]; }
        __syncthreads();
        #pragma unroll 4
        for(int m=0;m<32;m++){
            unsigned long long a2[4],b2[2];
            #pragma unroll
            for(int u=0;u<4;u++){ float av=sQ[(u*16+ty)*33+m]; a2[u]=pk2(av,av); }
            b2[0]=*(const unsigned long long*)&sKV[m*66+tx*2];
            b2[1]=*(const unsigned long long*)&sKV[m*66+32+tx*2];
            #pragma unroll
            for(int u=0;u<4;u++){
                FMA2(acc2[u][0],a2[u],b2[0],acc2[u][0]);
                FMA2(acc2[u][1],a2[u],b2[1],acc2[u][1]);
            }
        }
    }
    #pragma unroll
    for(int u=0;u<4;u++)
        #pragma unroll
        for(int w2=0;w2<2;w2++){
            float o0,o1; upk2(o0,o1,acc2[u][w2]);
            *(float2*)&d_qkv[((size_t)bh*Tn+t0+u*16+ty)*64+w2*32+tx*2]=make_float2(o0,o1);
        }
}

// dyn smem floats: A0 4352 | BT0 4224 | A1 4352 | BT1 4224 | meta 896  (no sInner)
#define S_A0 0
#define S_BT0 4352
#define S_A1 8576
#define S_BT1 12800
#define S_META 17024
#define ATTN_SMEM_BYTES ((S_META+896)*4)

__global__ void __launch_bounds__(512,1) k_attn(const float* __restrict__ q,
                                                const float* __restrict__ k,
                                                const float* __restrict__ v){
    extern __shared__ float dyn[];
    int* sQt=(int*)(dyn+S_META);
    int* sKt=(int*)(dyn+S_META+128);
    unsigned* sQC=(unsigned*)(dyn+S_META+256);
    unsigned* sKC=(unsigned*)(dyn+S_META+384);
    float* sPls=dyn+S_META+512;
    float* sLse=dyn+S_META+640;
    float* sPexp=dyn+S_META+768;
    int n=blockIdx.x,bh=blockIdx.y,h=blockIdx.z;
    int b=bh>>3,h2=bh&7,hb=h*BHn+bh;
    int tid=threadIdx.x,ty=tid>>4,tx=tid&15;
    if(tid<128){
        int qt=d_qpos[(size_t)hb*Tn+n*128+tid];
        int kt=d_kpos[(size_t)hb*Tn+n*128+tid];
        sQt[tid]=qt; sKt[tid]=kt;
        sQC[tid]=d_qcode[bh*Tn+qt]; sKC[tid]=d_kcode[bh*Tn+kt];
        sPls[tid]=d_pls[bh*Tn+qt];
    }
    __syncthreads();
    // ===== phase 1: inner = Q K^T =====
    unsigned long long accI[4][4];
    #pragma unroll
    for(int u=0;u<4;u++)
        #pragma unroll
        for(int w=0;w<4;w++) accI[u][w]=0ull;
    float4 qa[2],ka[2];
    #pragma unroll
    for(int j2=0;j2<2;j2++){
        int idx=tid+j2*512; int r=idx>>3,seg=idx&7;
        qa[j2]=*(const float4*)&q[((size_t)(b*Tn+sQt[r])*8+h2)*64+seg*4];
        ka[j2]=*(const float4*)&k[((size_t)(b*Tn+sKt[r])*8+h2)*64+seg*4];
    }
    {
        float* sA=dyn+S_A0; float* sBT=dyn+S_BT0;
        #pragma unroll
        for(int j2=0;j2<2;j2++){
            int idx=tid+j2*512; int r=idx>>3,seg=idx&7;
            sA[r*33+seg*4+0]=qa[j2].x; sA[r*33+seg*4+1]=qa[j2].y;
            sA[r*33+seg*4+2]=qa[j2].z; sA[r*33+seg*4+3]=qa[j2].w;
            sBT[(seg*4+0)*130+r]=ka[j2].x; sBT[(seg*4+1)*130+r]=ka[j2].y;
            sBT[(seg*4+2)*130+r]=ka[j2].z; sBT[(seg*4+3)*130+r]=ka[j2].w;
        }
    }
    #pragma unroll
    for(int j2=0;j2<2;j2++){
        int idx=tid+j2*512; int r=idx>>3,seg=idx&7;
        qa[j2]=*(const float4*)&q[((size_t)(b*Tn+sQt[r])*8+h2)*64+32+seg*4];
        ka[j2]=*(const float4*)&k[((size_t)(b*Tn+sKt[r])*8+h2)*64+32+seg*4];
    }
    __syncthreads();
    for(int ec=0;ec<2;ec++){
        float* sA=dyn+(ec?S_A1:S_A0); float* sBT=dyn+(ec?S_BT1:S_BT0);
        #pragma unroll 4
        for(int e=0;e<32;e++){
            unsigned long long a2[4],b2[4];
            #pragma unroll
            for(int u=0;u<4;u++){ float av=sA[(u*32+ty)*33+e]; a2[u]=pk2(av,av); }
            #pragma unroll
            for(int w=0;w<4;w++) b2[w]=*(const unsigned long long*)&sBT[e*130+w*32+tx*2];
            #pragma unroll
            for(int u=0;u<4;u++)
                #pragma unroll
                for(int w=0;w<4;w++) FMA2(accI[u][w],a2[u],b2[w],accI[u][w]);
        }
        if(ec==0){
            float* sA1=dyn+S_A1; float* sBT1=dyn+S_BT1;
            #pragma unroll
            for(int j2=0;j2<2;j2++){
                int idx=tid+j2*512; int r=idx>>3,seg=idx&7;
                sA1[r*33+seg*4+0]=qa[j2].x; sA1[r*33+seg*4+1]=qa[j2].y;
                sA1[r*33+seg*4+2]=qa[j2].z; sA1[r*33+seg*4+3]=qa[j2].w;
                sBT1[(seg*4+0)*130+r]=ka[j2].x; sBT1[(seg*4+1)*130+r]=ka[j2].y;
                sBT1[(seg*4+2)*130+r]=ka[j2].z; sBT1[(seg*4+3)*130+r]=ka[j2].w;
            }
            __syncthreads();
        }
    }
    // epilogue: keep inner in registers (packed), compute lse
    const float ldt[4]={0.f,0.6931471805599453f,1.0986122886681098f,1.3862943611198906f};
    #pragma unroll
    for(int u=0;u<4;u++){
        int i=u*32+ty;
        unsigned qc=sQC[i];
        float rm=-3.4e38f;
        #pragma unroll
        for(int w=0;w<4;w++){
            int j0=w*32+tx*2;
            float v0,v1; upk2(v0,v1,accI[u][w]);
            int dup0=__popc(__vcmpeq4(qc,sKC[j0]))>>3;
            int dup1=__popc(__vcmpeq4(qc,sKC[j0+1]))>>3;
            float val0=v0*0.125f-ldt[dup0-1];
            float val1=v1*0.125f-ldt[dup1-1];
            accI[u][w]=pk2(val0,val1);
            rm=fmaxf(rm,fmaxf(val0,val1));
        }
        #pragma unroll
        for(int o=8;o;o>>=1) rm=fmaxf(rm,__shfl_xor_sync(0xffffffffu,rm,o,16));
        if(tx==0){
            float l=fmaxf(rm,sPls[i]);
            sLse[i]=l; sPexp[i]=__expf(sPls[i]-l);
        }
    }
    // ===== phase 2: dots_prime = q' k'^T =====
    unsigned long long accP[4][4];
    #pragma unroll
    for(int u=0;u<4;u++)
        #pragma unroll
        for(int w=0;w<4;w++) accP[u][w]=0ull;
    float4 pa[2],pb[2];
    #pragma unroll
    for(int j2=0;j2<2;j2++){
        int idx=tid+j2*512; int r=idx>>3,seg=idx&7;
        pa[j2]=*(const float4*)&d_qprime[((size_t)bh*Tn+sQt[r])*256+seg*4];
        pb[j2]=*(const float4*)&d_kprime[((size_t)bh*Tn+sKt[r])*256+seg*4];
    }
    {
        float* sA=dyn+S_A0; float* sBT=dyn+S_BT0;
        #pragma unroll
        for(int j2=0;j2<2;j2++){
            int idx=tid+j2*512; int r=idx>>3,seg=idx&7;
            sA[r*33+seg*4+0]=pa[j2].x; sA[r*33+seg*4+1]=pa[j2].y;
            sA[r*33+seg*4+2]=pa[j2].z; sA[r*33+seg*4+3]=pa[j2].w;
            sBT[(seg*4+0)*130+r]=pb[j2].x; sBT[(seg*4+1)*130+r]=pb[j2].y;
            sBT[(seg*4+2)*130+r]=pb[j2].z; sBT[(seg*4+3)*130+r]=pb[j2].w;
        }
    }
    #pragma unroll
    for(int j2=0;j2<2;j2++){
        int idx=tid+j2*512; int r=idx>>3,seg=idx&7;
        pa[j2]=*(const float4*)&d_qprime[((size_t)bh*Tn+sQt[r])*256+32+seg*4];
        pb[j2]=*(const float4*)&d_kprime[((size_t)bh*Tn+sKt[r])*256+32+seg*4];
    }
    __syncthreads();
    for(int c=0;c<8;c++){
        if(c<7){
            float* sA=dyn+(((c+1)&1)?S_A1:S_A0); float* sBT=dyn+(((c+1)&1)?S_BT1:S_BT0);
            #pragma unroll
            for(int j2=0;j2<2;j2++){
                int idx=tid+j2*512; int r=idx>>3,seg=idx&7;
                sA[r*33+seg*4+0]=pa[j2].x; sA[r*33+seg*4+1]=pa[j2].y;
                sA[r*33+seg*4+2]=pa[j2].z; sA[r*33+seg*4+3]=pa[j2].w;
                sBT[(seg*4+0)*130+r]=pb[j2].x; sBT[(seg*4+1)*130+r]=pb[j2].y;
                sBT[(seg*4+2)*130+r]=pb[j2].z; sBT[(seg*4+3)*130+r]=pb[j2].w;
            }
            if(c<6){
                #pragma unroll
                for(int j2=0;j2<2;j2++){
                    int idx=tid+j2*512; int r=idx>>3,seg=idx&7;
                    pa[j2]=*(const float4*)&d_qprime[((size_t)bh*Tn+sQt[r])*256+(c+2)*32+seg*4];
                    pb[j2]=*(const float4*)&d_kprime[((size_t)bh*Tn+sKt[r])*256+(c+2)*32+seg*4];
                }
            }
        }
        float* sA=dyn+((c&1)?S_A1:S_A0); float* sBT=dyn+((c&1)?S_BT1:S_BT0);
        #pragma unroll 4
        for(int m=0;m<32;m++){
            unsigned long long a2[4],b2[4];
            #pragma unroll
            for(int u=0;u<4;u++){ float av=sA[(u*32+ty)*33+m]; a2[u]=pk2(av,av); }
            #pragma unroll
            for(int w=0;w<4;w++) b2[w]=*(const unsigned long long*)&sBT[m*130+w*32+tx*2];
            #pragma unroll
            for(int u=0;u<4;u++)
                #pragma unroll
                for(int w=0;w<4;w++) FMA2(accP[u][w],a2[u],b2[w],accP[u][w]);
        }
        __syncthreads();
    }
    // ===== phase 3: dots + dots@V =====
    float* sDots=dyn+S_A0;
    float* sV=dyn+S_BT0;
    unsigned long long accO[4][2];
    #pragma unroll
    for(int u=0;u<4;u++){ accO[u][0]=0ull; accO[u][1]=0ull; }
    float rsum[4]={};
    for(int jc=0;jc<4;jc++){
        if(jc) __syncthreads();
        #pragma unroll
        for(int u=0;u<4;u++){
            int i=u*32+ty;
            float lse=sLse[i],pe=sPexp[i];
            unsigned qc=sQC[i];
            int j0=jc*32+tx*2;
            float p0,p1; upk2(p0,p1,accP[u][jc]);
            float in0,in1; upk2(in0,in1,accI[u][jc]);
            int dup0=__popc(__vcmpeq4(qc,sKC[j0]))>>3;
            int dup1=__popc(__vcmpeq4(qc,sKC[j0+1]))>>3;
            float dots0=__expf(in0-lse)-(p0/(float)dup0)*pe;
            float dots1=__expf(in1-lse)-(p1/(float)dup1)*pe;
            rsum[u]+=dots0+dots1;
            *(float2*)&sDots[i*34+tx*2]=make_float2(dots0,dots1);
        }
        {
            int jj=tid>>4, seg=tid&15;
            float4 va=*(const float4*)&v[((size_t)(b*Tn+sKt[jc*32+jj])*8+h2)*64+seg*4];
            *(float2*)&sV[jj*66+seg*4]=make_float2(va.x,va.y);
            *(float2*)&sV[jj*66+seg*4+2]=make_float2(va.z,va.w);
        }
        __syncthreads();
        #pragma unroll 4
        for(int jj=0;jj<32;jj++){
            unsigned long long dv2[4],vv2[2];
            #pragma unroll
            for(int u=0;u<4;u++){ float dvv=sDots[(u*32+ty)*34+jj]; dv2[u]=pk2(dvv,dvv); }
            vv2[0]=*(const unsigned long long*)&sV[jj*66+tx*2];
            vv2[1]=*(const unsigned long long*)&sV[jj*66+32+tx*2];
            #pragma unroll
            for(int u=0;u<4;u++){
                FMA2(accO[u][0],dv2[u],vv2[0],accO[u][0]);
                FMA2(accO[u][1],dv2[u],vv2[1],accO[u][1]);
            }
        }
    }
    #pragma unroll
    for(int u=0;u<4;u++){
        int i=u*32+ty;
        int qt=sQt[i];
        float rs=rsum[u];
        #pragma unroll
        for(int o=8;o;o>>=1) rs+=__shfl_xor_sync(0xffffffffu,rs,o,16);
        if(tx==0){
            d_logits[(size_t)hb*Tn+qt]=sLse[i];
            d_dsumg[(size_t)hb*Tn+qt]=rs;
        }
        #pragma unroll
        for(int w2=0;w2<2;w2++){
            float o0,o1; upk2(o0,o1,accO[u][w2]);
            *(float2*)&d_obuf[((size_t)hb*Tn+qt)*64+w2*32+tx*2]=make_float2(o0,o1);
        }
    }
}

__global__ void k_final(float* __restrict__ out){
    int gid=blockIdx.x*256+threadIdx.x;
    int bh=gid>>14,rr=gid&16383,t=rr>>2,gq=rr&3;
    int g=bh*Tn+t;
    float l[4],ds[4];
    #pragma unroll
    for(int h=0;h<4;h++){ l[h]=d_logits[(size_t)(h*BHn+bh)*Tn+t]; ds[h]=d_dsumg[(size_t)(h*BHn+bh)*Tn+t]; }
    float m=fmaxf(fmaxf(l[0],l[1]),fmaxf(l[2],l[3]));
    float s=__expf(l[0]-m)+__expf(l[1]-m)+__expf(l[2]-m)+__expf(l[3]-m);
    float nls=m+__logf(s);
    float ps=__expf(d_pls[g]-nls);
    float p[4];
    float norm=d_qk1[g]*ps;
    #pragma unroll
    for(int h=0;h<4;h++){ p[h]=__expf(l[h]-nls); norm=fmaf(ds[h],p[h],norm); }
    norm=fmaxf(norm,1e-6f);
    float inv=1.f/norm;
    int b=bh>>3,h2=bh&7;
    const float4* qkv4=(const float4*)(d_qkv+(size_t)g*64+gq*16);
    float4* o4=(float4*)(out+((size_t)(b*Tn+t)*8+h2)*64+gq*16);
    #pragma unroll
    for(int j=0;j<4;j++){
        float4 a=qkv4[j];
        float4 r; r.x=a.x*ps; r.y=a.y*ps; r.z=a.z*ps; r.w=a.w*ps;
        #pragma unroll
        for(int h=0;h<4;h++){
            const float4 ob=((const float4*)(d_obuf+((size_t)(h*BHn+bh)*Tn+t)*64+gq*16))[j];
            r.x=fmaf(ob.x,p[h],r.x); r.y=fmaf(ob.y,p[h],r.y);
            r.z=fmaf(ob.z,p[h],r.z); r.w=fmaf(ob.w,p[h],r.w);
        }
        r.x*=inv; r.y*=inv; r.z*=inv; r.w*=inv;
        o4[j]=r;
    }
}

extern "C" void kernel_launch(void* const* d_in, const int* in_sizes, int n_in,
                              void* d_out, int out_size){
    const float* q=(const float*)d_in[0];
    const float* k=(const float*)d_in[1];
    const float* v=(const float*)d_in[2];
    const float* proj=(const float*)d_in[3];
    const float* alpha=(const float*)d_in[4];
    const float* beta=(const float*)d_in[5];
    float* out=(float*)d_out;
    cudaFuncSetAttribute(k_attn, cudaFuncAttributeMaxDynamicSharedMemorySize, ATTN_SMEM_BYTES);
    k_init<<<1024,256>>>();
    k_norms<<<256,256>>>(q,k);
    k_hash<<<512,256>>>(q,k,alpha,beta);
    k_sort<<<128,1024>>>();
    k_featmax<<<1024,256>>>(k,proj);
    k_kv<<<dim3(8,4,16),256>>>(v);
    k_qfeatg<<<1024,256>>>(q,proj);
    k_qkv<<<dim3(64,16),256>>>();
    k_attn<<<dim3(32,16,4),512,ATTN_SMEM_BYTES>>>(q,k,v);
    k_final<<<1024,256>>>(out);
}